// round 4
// baseline (speedup 1.0000x reference)
#include <cuda_runtime.h>
#include <math.h>

#define S_LEN 2048
#define NB 2
#define NH 16
#define NKV 4
#define HD 128
#define HDIM 2048

// Scratch (allocation-free rule: __device__ globals)
__device__ float g_q[NB * NH * S_LEN * HD];    // [b][h][s][d]
__device__ float g_k[NB * NKV * S_LEN * HD];   // [b][kh][s][d]
__device__ float g_v[NB * NKV * S_LEN * HD];   // [b][kh][s][d]
__device__ float g_ao[NB * S_LEN * NH * HD];   // [b][s][h*128+d]

// ---------------------------------------------------------------------------
// NT GEMM: C[M,N] = A[M,K] * B[N,K]^T   (both row-major, K contiguous)
// BM=BN=128, BK=16, 256 threads, 8x8 fragments.
// scatter=1: write C[i,j] to [( (i>>11)*Htot + (j>>7) )*S + (i&2047)]*128 + (j&127)
// ---------------------------------------------------------------------------
__global__ __launch_bounds__(256, 2) void gemm_nt_kernel(
    const float* __restrict__ A, const float* __restrict__ B,
    float* __restrict__ C, int K, int N, int Htot, int scatter)
{
    __shared__ float As[16][132];
    __shared__ float Bs[16][132];

    const int tid = threadIdx.x;
    const int tr = tid >> 4;          // 0..15
    const int tc = tid & 15;          // 0..15
    const int row0 = blockIdx.y * 128;
    const int col0 = blockIdx.x * 128;
    const int lr = tid >> 2;          // 0..63
    const int lc = (tid & 3) * 4;     // 0,4,8,12

    float acc[8][8];
#pragma unroll
    for (int i = 0; i < 8; i++)
#pragma unroll
        for (int j = 0; j < 8; j++) acc[i][j] = 0.f;

    for (int k0 = 0; k0 < K; k0 += 16) {
        float4 a0 = *(const float4*)&A[(row0 + lr) * K + k0 + lc];
        float4 a1 = *(const float4*)&A[(row0 + lr + 64) * K + k0 + lc];
        float4 b0 = *(const float4*)&B[(col0 + lr) * K + k0 + lc];
        float4 b1 = *(const float4*)&B[(col0 + lr + 64) * K + k0 + lc];
        __syncthreads();
        As[lc + 0][lr] = a0.x; As[lc + 1][lr] = a0.y;
        As[lc + 2][lr] = a0.z; As[lc + 3][lr] = a0.w;
        As[lc + 0][lr + 64] = a1.x; As[lc + 1][lr + 64] = a1.y;
        As[lc + 2][lr + 64] = a1.z; As[lc + 3][lr + 64] = a1.w;
        Bs[lc + 0][lr] = b0.x; Bs[lc + 1][lr] = b0.y;
        Bs[lc + 2][lr] = b0.z; Bs[lc + 3][lr] = b0.w;
        Bs[lc + 0][lr + 64] = b1.x; Bs[lc + 1][lr + 64] = b1.y;
        Bs[lc + 2][lr + 64] = b1.z; Bs[lc + 3][lr + 64] = b1.w;
        __syncthreads();
#pragma unroll
        for (int kk = 0; kk < 16; kk++) {
            float ar[8], br[8];
            *(float4*)&ar[0] = *(const float4*)&As[kk][tr * 8];
            *(float4*)&ar[4] = *(const float4*)&As[kk][tr * 8 + 4];
            *(float4*)&br[0] = *(const float4*)&Bs[kk][tc * 8];
            *(float4*)&br[4] = *(const float4*)&Bs[kk][tc * 8 + 4];
#pragma unroll
            for (int i = 0; i < 8; i++)
#pragma unroll
                for (int j = 0; j < 8; j++)
                    acc[i][j] = fmaf(ar[i], br[j], acc[i][j]);
        }
    }

    if (scatter) {
#pragma unroll
        for (int i = 0; i < 8; i++) {
            int gi = row0 + tr * 8 + i;
            int bb = gi >> 11, ss = gi & 2047;
#pragma unroll
            for (int j = 0; j < 8; j++) {
                int gj = col0 + tc * 8 + j;
                int hh = gj >> 7, dd = gj & 127;
                C[((bb * Htot + hh) * S_LEN + ss) * HD + dd] = acc[i][j];
            }
        }
    } else {
#pragma unroll
        for (int i = 0; i < 8; i++) {
            int gi = row0 + tr * 8 + i;
#pragma unroll
            for (int j = 0; j < 8; j++)
                C[(size_t)gi * N + col0 + tc * 8 + j] = acc[i][j];
        }
    }
}

// ---------------------------------------------------------------------------
// RoPE in-place on [BH][S][128]: pairs (i, i+64), i in [0,64)
// ---------------------------------------------------------------------------
__global__ void rope_kernel(float* __restrict__ x, int total)
{
    int idx = blockIdx.x * blockDim.x + threadIdx.x;
    if (idx >= total) return;
    int i = idx & 63;
    int r = idx >> 6;                 // bh*S + s
    int s = r & (S_LEN - 1);
    float inv = powf(10000.0f, -(float)i / 64.0f);
    float f = (float)s * inv;
    float sv, cv;
    sincosf(f, &sv, &cv);
    float* p = x + (size_t)r * HD;
    float x1 = p[i], x2 = p[i + 64];
    p[i]      = x1 * cv - x2 * sv;
    p[i + 64] = x2 * cv + x1 * sv;
}

// ---------------------------------------------------------------------------
// Flash attention fp32, non-causal. Per block: 128 q rows of (b,h).
// Tiles of 64 keys. 256 threads (16x16), per-thread: 8 q-rows x 4 key-cols
// for scores, 8 q-rows x 8 d-cols for O.
// Qs stride is 129 (r index runs 0..127) — the round-1 bug was stride 65 here.
// ---------------------------------------------------------------------------
#define SMEM_FLASH ((128*129 + 128*65 + 64*128 + 64*129 + 128*16*2) * 4)

__global__ __launch_bounds__(256, 1) void flash_kernel()
{
    extern __shared__ float sm[];
    float* Qs   = sm;                    // [d=128][r=128] stride 129 -> Qs[d*129+r]
    float* Ks   = Qs + 128 * 129;        // [d=128][c=64]  stride 65  -> Ks[d*65+c]
    float* Vs   = Ks + 128 * 65;         // [j=64][dd=128] -> Vs[j*128+dd]
    float* Ps   = Vs + 64 * 128;         // [j=64][r=128]  stride 129 -> Ps[j*129+r]
    float* redA = Ps + 64 * 129;         // [r=128][t=16]
    float* redB = redA + 128 * 16;

    const int tid = threadIdx.x;
    const int tr = tid >> 4;             // 0..15 -> rows tr*8..+7
    const int tc = tid & 15;             // 0..15
    const int b = blockIdx.z, h = blockIdx.y;
    const int q0 = blockIdx.x * 128;
    const int kvh = h >> 2;

    const float* Qg = g_q + (((size_t)b * NH + h) * S_LEN + q0) * HD;
    const float* Kg = g_k + (((size_t)b * NKV + kvh) * S_LEN) * HD;
    const float* Vg = g_v + (((size_t)b * NKV + kvh) * S_LEN) * HD;

    // Load Q tile transposed: Qs[d][r]
    for (int idx = tid; idx < 128 * 32; idx += 256) {
        int r = idx >> 5, d4 = (idx & 31) * 4;
        float4 v = *(const float4*)&Qg[r * HD + d4];
        Qs[(d4 + 0) * 129 + r] = v.x;
        Qs[(d4 + 1) * 129 + r] = v.y;
        Qs[(d4 + 2) * 129 + r] = v.z;
        Qs[(d4 + 3) * 129 + r] = v.w;
    }

    float m_r[8], l_r[8], O[8][8];
#pragma unroll
    for (int i = 0; i < 8; i++) {
        m_r[i] = -1e30f;
        l_r[i] = 0.f;
#pragma unroll
        for (int c = 0; c < 8; c++) O[i][c] = 0.f;
    }
    const float scale = 0.08838834764831845f;  // 1/sqrt(128)

    for (int k0 = 0; k0 < S_LEN; k0 += 64) {
        __syncthreads();  // previous tile's K/V/P reads complete (covers Q load too)
        // Load K (transposed) and V tiles
        for (int idx = tid; idx < 64 * 32; idx += 256) {
            int c = idx >> 5, d4 = (idx & 31) * 4;
            float4 kv = *(const float4*)&Kg[(k0 + c) * HD + d4];
            Ks[(d4 + 0) * 65 + c] = kv.x;
            Ks[(d4 + 1) * 65 + c] = kv.y;
            Ks[(d4 + 2) * 65 + c] = kv.z;
            Ks[(d4 + 3) * 65 + c] = kv.w;
            float4 vv = *(const float4*)&Vg[(k0 + c) * HD + d4];
            *(float4*)&Vs[c * 128 + d4] = vv;
        }
        __syncthreads();

        // Scores: sc[8][4] = Q[r,:] . K[c,:]
        float sc[8][4];
#pragma unroll
        for (int i = 0; i < 8; i++)
#pragma unroll
            for (int j = 0; j < 4; j++) sc[i][j] = 0.f;

#pragma unroll 2
        for (int d = 0; d < 128; d++) {
            float qa[8], kb[4];
#pragma unroll
            for (int i = 0; i < 8; i++) qa[i] = Qs[d * 129 + tr * 8 + i];
#pragma unroll
            for (int j = 0; j < 4; j++) kb[j] = Ks[d * 65 + tc * 4 + j];
#pragma unroll
            for (int i = 0; i < 8; i++)
#pragma unroll
                for (int j = 0; j < 4; j++)
                    sc[i][j] = fmaf(qa[i], kb[j], sc[i][j]);
        }
#pragma unroll
        for (int i = 0; i < 8; i++)
#pragma unroll
            for (int j = 0; j < 4; j++) sc[i][j] *= scale;

        // Phase 1: local row max
#pragma unroll
        for (int i = 0; i < 8; i++) {
            float lm = sc[i][0];
            lm = fmaxf(lm, sc[i][1]);
            lm = fmaxf(lm, sc[i][2]);
            lm = fmaxf(lm, sc[i][3]);
            redA[(tr * 8 + i) * 16 + tc] = lm;
        }
        __syncthreads();

        // Phase 2: new max, rescale O, exp, write P, local sums
        float alpha_r[8];
#pragma unroll
        for (int i = 0; i < 8; i++) {
            int row = tr * 8 + i;
            float mx = m_r[i];
#pragma unroll
            for (int t = 0; t < 16; t++) mx = fmaxf(mx, redA[row * 16 + t]);
            alpha_r[i] = __expf(m_r[i] - mx);
            m_r[i] = mx;
#pragma unroll
            for (int c = 0; c < 8; c++) O[i][c] *= alpha_r[i];
            float ls = 0.f;
#pragma unroll
            for (int j = 0; j < 4; j++) {
                float p = __expf(sc[i][j] - mx);
                ls += p;
                Ps[(tc * 4 + j) * 129 + row] = p;
            }
            redB[row * 16 + tc] = ls;
        }
        __syncthreads();

        // Phase 3: l update
#pragma unroll
        for (int i = 0; i < 8; i++) {
            int row = tr * 8 + i;
            float rs = 0.f;
#pragma unroll
            for (int t = 0; t < 16; t++) rs += redB[row * 16 + t];
            l_r[i] = l_r[i] * alpha_r[i] + rs;
        }

        // PV: O[r][d] += sum_j P[r][j] * V[j][d]
#pragma unroll 2
        for (int j = 0; j < 64; j++) {
            float pa[8], vb[8];
#pragma unroll
            for (int i = 0; i < 8; i++) pa[i] = Ps[j * 129 + tr * 8 + i];
            *(float4*)&vb[0] = *(const float4*)&Vs[j * 128 + tc * 8];
            *(float4*)&vb[4] = *(const float4*)&Vs[j * 128 + tc * 8 + 4];
#pragma unroll
            for (int i = 0; i < 8; i++)
#pragma unroll
                for (int c = 0; c < 8; c++)
                    O[i][c] = fmaf(pa[i], vb[c], O[i][c]);
        }
    }

    // Final normalize and store to [b][s][h*128+d]
#pragma unroll
    for (int i = 0; i < 8; i++) {
        int row = tr * 8 + i;
        float inv = 1.0f / l_r[i];
        float* dst = g_ao + ((size_t)(b * S_LEN + q0 + row)) * HDIM + h * HD + tc * 8;
#pragma unroll
        for (int c = 0; c < 8; c++) dst[c] = O[i][c] * inv;
    }
}

// ---------------------------------------------------------------------------
extern "C" void kernel_launch(void* const* d_in, const int* in_sizes, int n_in,
                              void* d_out, int out_size)
{
    const float* hs = (const float*)d_in[0];
    const float* Wq = (const float*)d_in[1];
    const float* Wk = (const float*)d_in[2];
    const float* Wv = (const float*)d_in[3];
    const float* Wo = (const float*)d_in[4];
    float* out = (float*)d_out;

    float *qp, *kp, *vp, *aop;
    cudaGetSymbolAddress((void**)&qp, g_q);
    cudaGetSymbolAddress((void**)&kp, g_k);
    cudaGetSymbolAddress((void**)&vp, g_v);
    cudaGetSymbolAddress((void**)&aop, g_ao);

    cudaFuncSetAttribute(flash_kernel,
                         cudaFuncAttributeMaxDynamicSharedMemorySize, SMEM_FLASH);

    // QKV projections with head-layout scatter
    gemm_nt_kernel<<<dim3(16, 32), 256>>>(hs, Wq, qp, HDIM, NH * HD, NH, 1);
    gemm_nt_kernel<<<dim3(4, 32), 256>>>(hs, Wk, kp, HDIM, NKV * HD, NKV, 1);
    gemm_nt_kernel<<<dim3(4, 32), 256>>>(hs, Wv, vp, HDIM, NKV * HD, NKV, 1);

    // RoPE on q and k
    rope_kernel<<<(NB * NH * S_LEN * 64) / 256, 256>>>(qp, NB * NH * S_LEN * 64);
    rope_kernel<<<(NB * NKV * S_LEN * 64) / 256, 256>>>(kp, NB * NKV * S_LEN * 64);

    // Attention
    flash_kernel<<<dim3(16, NH, NB), 256, SMEM_FLASH>>>();

    // Output projection
    gemm_nt_kernel<<<dim3(16, 32), 256>>>(aop, Wo, out, HDIM, HDIM, 0, 0);
}

// round 6
// speedup vs baseline: 1.3553x; 1.3553x over previous
#include <cuda_runtime.h>
#include <cuda_bf16.h>
#include <math.h>
#include <stdint.h>

#define S_LEN 2048
#define NB 2
#define NH 16
#define NKV 4
#define HD 128
#define HDIM 2048
#define GK 2048

// ---------------- fp32 scratch ----------------
__device__ float g_q[NB * NH * S_LEN * HD];    // [b][h][s][d]
__device__ float g_k[NB * NKV * S_LEN * HD];
__device__ float g_v[NB * NKV * S_LEN * HD];
__device__ float g_ao[NB * S_LEN * NH * HD];   // [b][s][h*128+d]

// ---------------- bf16 split scratch ----------------
__device__ __nv_bfloat16 g_hs_hi[NB * S_LEN * HDIM], g_hs_lo[NB * S_LEN * HDIM];
__device__ __nv_bfloat16 g_wq_hi[NH * HD * HDIM],    g_wq_lo[NH * HD * HDIM];
__device__ __nv_bfloat16 g_wk_hi[NKV * HD * HDIM],   g_wk_lo[NKV * HD * HDIM];
__device__ __nv_bfloat16 g_wv_hi[NKV * HD * HDIM],   g_wv_lo[NKV * HD * HDIM];
__device__ __nv_bfloat16 g_wo_hi[HDIM * HDIM],       g_wo_lo[HDIM * HDIM];
__device__ __nv_bfloat16 g_ao_hi[NB * S_LEN * HDIM], g_ao_lo[NB * S_LEN * HDIM];

// ---------------- HMMA helpers (sm_80+ PTX, valid on plain sm_103 target) ---
__device__ __forceinline__ uint32_t smem_u32(const void* p) {
    uint32_t a;
    asm("{ .reg .u64 t; cvta.to.shared.u64 t, %1; cvt.u32.u64 %0, t; }" : "=r"(a) : "l"(p));
    return a;
}
__device__ __forceinline__ void ldsm4(uint32_t& r0, uint32_t& r1, uint32_t& r2, uint32_t& r3,
                                      uint32_t addr) {
    asm volatile("ldmatrix.sync.aligned.m8n8.x4.shared.b16 {%0,%1,%2,%3}, [%4];"
                 : "=r"(r0), "=r"(r1), "=r"(r2), "=r"(r3) : "r"(addr));
}
__device__ __forceinline__ void ldsm2(uint32_t& r0, uint32_t& r1, uint32_t addr) {
    asm volatile("ldmatrix.sync.aligned.m8n8.x2.shared.b16 {%0,%1}, [%2];"
                 : "=r"(r0), "=r"(r1) : "r"(addr));
}
__device__ __forceinline__ void mma16816(float* c, const uint32_t* a, const uint32_t* b) {
    asm volatile(
        "mma.sync.aligned.m16n8k16.row.col.f32.bf16.bf16.f32 "
        "{%0,%1,%2,%3}, {%4,%5,%6,%7}, {%8,%9}, {%0,%1,%2,%3};"
        : "+f"(c[0]), "+f"(c[1]), "+f"(c[2]), "+f"(c[3])
        : "r"(a[0]), "r"(a[1]), "r"(a[2]), "r"(a[3]), "r"(b[0]), "r"(b[1]));
}

// ---------------- fp32 -> (hi, lo) bf16 split ----------------
__global__ void cvt_kernel(const float* __restrict__ x, __nv_bfloat16* __restrict__ hi,
                           __nv_bfloat16* __restrict__ lo, int n4)
{
    int i = blockIdx.x * 256 + threadIdx.x;
    if (i >= n4) return;
    float4 v = ((const float4*)x)[i];
    float vs[4] = {v.x, v.y, v.z, v.w};
    uint32_t hw[4], lw[4];
#pragma unroll
    for (int j = 0; j < 4; j++) {
        __nv_bfloat16 h = __float2bfloat16(vs[j]);
        float r = vs[j] - __bfloat162float(h);
        __nv_bfloat16 l = __float2bfloat16(r);
        hw[j] = (uint32_t)__bfloat16_as_ushort(h);
        lw[j] = (uint32_t)__bfloat16_as_ushort(l);
    }
    ((uint2*)hi)[i] = make_uint2(hw[0] | (hw[1] << 16), hw[2] | (hw[3] << 16));
    ((uint2*)lo)[i] = make_uint2(lw[0] | (lw[1] << 16), lw[2] | (lw[3] << 16));
}

// ---------------- HMMA split-bf16 NT GEMM --------------------------------
// C[M,N] = (Ah+Al)[M,K] * (Bh+Bl)[N,K]^T  (drop lo*lo), fp32 accum.
// Tile 128x128 per CTA, BK=32. 8 warps: warp_m = wid&1 (64 rows),
// warp_n = wid>>1 (32 cols). Per warp: 4x4 grid of m16n8 mma tiles.
// smem row stride 40 bf16 (32 + 8 pad) -> conflict-free ldmatrix.
#define ASTRIDE 40
#define TILE_BF (128 * ASTRIDE)          // elements per part

__global__ __launch_bounds__(256, 2) void gemm_mma_kernel(
    const __nv_bfloat16* __restrict__ Ah, const __nv_bfloat16* __restrict__ Al,
    const __nv_bfloat16* __restrict__ Bh, const __nv_bfloat16* __restrict__ Bl,
    float* __restrict__ C, int Htot, int scatter)
{
    __shared__ __nv_bfloat16 sm[4 * TILE_BF];  // Ah | Al | Bh | Bl
    __nv_bfloat16* sAh = sm;
    __nv_bfloat16* sAl = sm + TILE_BF;
    __nv_bfloat16* sBh = sm + 2 * TILE_BF;
    __nv_bfloat16* sBl = sm + 3 * TILE_BF;

    const int tid = threadIdx.x, wid = tid >> 5, lane = tid & 31;
    const int warp_m = wid & 1, warp_n = wid >> 1;
    const int row0 = blockIdx.y * 128, col0 = blockIdx.x * 128;

    float acc[4][4][4];
#pragma unroll
    for (int mi = 0; mi < 4; mi++)
#pragma unroll
        for (int ni = 0; ni < 4; ni++)
#pragma unroll
            for (int q = 0; q < 4; q++) acc[mi][ni][q] = 0.f;

    // ldmatrix per-thread base addresses (bf16-unit offsets)
    const int l15 = lane & 15;
    const int a_row = warp_m * 64 + l15;          // + mi*16
    const int a_kof = (lane >> 4) * 8;
    const int b_row = warp_n * 32 + (l15 & 7);    // + ni*8
    const int b_kof = (l15 >> 3) * 8;
    uint32_t sa_h = smem_u32(sAh), sa_l = smem_u32(sAl);
    uint32_t sb_h = smem_u32(sBh), sb_l = smem_u32(sBl);

    for (int kc = 0; kc < GK; kc += 32) {
        __syncthreads();
        // Load 4 parts: each 128 rows x 32 bf16 = 512 uint4; 2 per thread per part.
#pragma unroll
        for (int part = 0; part < 4; part++) {
            const __nv_bfloat16* src = (part == 0) ? Ah : (part == 1) ? Al : (part == 2) ? Bh : Bl;
            int rbase = (part < 2) ? row0 : col0;
            __nv_bfloat16* dst = sm + part * TILE_BF;
#pragma unroll
            for (int j = 0; j < 2; j++) {
                int idx = tid * 2 + j;                 // 0..511
                int r = idx >> 2, c = idx & 3;         // row, 8-elt chunk
                uint4 v = *(const uint4*)&src[(size_t)(rbase + r) * GK + kc + c * 8];
                *(uint4*)&dst[r * ASTRIDE + c * 8] = v;
            }
        }
        __syncthreads();

#pragma unroll
        for (int ks = 0; ks < 2; ks++) {
            uint32_t bh[4][2], bl[4][2];
#pragma unroll
            for (int ni = 0; ni < 4; ni++) {
                uint32_t off = ((b_row + ni * 8) * ASTRIDE + ks * 16 + b_kof) * 2;
                ldsm2(bh[ni][0], bh[ni][1], sb_h + off);
                ldsm2(bl[ni][0], bl[ni][1], sb_l + off);
            }
#pragma unroll
            for (int mi = 0; mi < 4; mi++) {
                uint32_t ah[4], al[4];
                uint32_t off = ((a_row + mi * 16) * ASTRIDE + ks * 16 + a_kof) * 2;
                ldsm4(ah[0], ah[1], ah[2], ah[3], sa_h + off);
                ldsm4(al[0], al[1], al[2], al[3], sa_l + off);
#pragma unroll
                for (int ni = 0; ni < 4; ni++) {
                    mma16816(acc[mi][ni], ah, bh[ni]);
                    mma16816(acc[mi][ni], al, bh[ni]);
                    mma16816(acc[mi][ni], ah, bl[ni]);
                }
            }
        }
    }

    // Epilogue: c0,c1 at (r, cc), c2,c3 at (r+8, cc)
    const int er = warp_m * 64 + (lane >> 2);
    const int ec = warp_n * 32 + (lane & 3) * 2;
    if (scatter) {
        const int h = col0 >> 7;
#pragma unroll
        for (int mi = 0; mi < 4; mi++) {
#pragma unroll
            for (int ni = 0; ni < 4; ni++) {
                int cc = ec + ni * 8;
#pragma unroll
                for (int half = 0; half < 2; half++) {
                    int gi = row0 + er + mi * 16 + half * 8;
                    int b = gi >> 11, s = gi & 2047;
                    float* dst = &C[(((size_t)b * Htot + h) * S_LEN + s) * HD + cc];
                    dst[0] = acc[mi][ni][half * 2 + 0];
                    dst[1] = acc[mi][ni][half * 2 + 1];
                }
            }
        }
    } else {
#pragma unroll
        for (int mi = 0; mi < 4; mi++) {
#pragma unroll
            for (int ni = 0; ni < 4; ni++) {
                int cc = col0 + ec + ni * 8;
#pragma unroll
                for (int half = 0; half < 2; half++) {
                    int gi = row0 + er + mi * 16 + half * 8;
                    float* dst = &C[(size_t)gi * HDIM + cc];
                    dst[0] = acc[mi][ni][half * 2 + 0];
                    dst[1] = acc[mi][ni][half * 2 + 1];
                }
            }
        }
    }
}

// ---------------------------------------------------------------------------
// RoPE in-place on [BH][S][128]: pairs (i, i+64), i in [0,64)
// ---------------------------------------------------------------------------
__global__ void rope_kernel(float* __restrict__ x, int total)
{
    int idx = blockIdx.x * blockDim.x + threadIdx.x;
    if (idx >= total) return;
    int i = idx & 63;
    int r = idx >> 6;
    int s = r & (S_LEN - 1);
    float inv = powf(10000.0f, -(float)i / 64.0f);
    float f = (float)s * inv;
    float sv, cv;
    sincosf(f, &sv, &cv);
    float* p = x + (size_t)r * HD;
    float x1 = p[i], x2 = p[i + 64];
    p[i]      = x1 * cv - x2 * sv;
    p[i + 64] = x2 * cv + x1 * sv;
}

// ---------------------------------------------------------------------------
// Flash attention fp32, non-causal (unchanged from passing round 4 kernel).
// ---------------------------------------------------------------------------
#define SMEM_FLASH ((128*129 + 128*65 + 64*128 + 64*129 + 128*16*2) * 4)

__global__ __launch_bounds__(256, 1) void flash_kernel()
{
    extern __shared__ float smf[];
    float* Qs   = smf;                   // [d=128][r=128] stride 129
    float* Ks   = Qs + 128 * 129;        // [d=128][c=64]  stride 65
    float* Vs   = Ks + 128 * 65;         // [j=64][dd=128]
    float* Ps   = Vs + 64 * 128;         // [j=64][r=128]  stride 129
    float* redA = Ps + 64 * 129;         // [r=128][t=16]
    float* redB = redA + 128 * 16;

    const int tid = threadIdx.x;
    const int tr = tid >> 4;
    const int tc = tid & 15;
    const int b = blockIdx.z, h = blockIdx.y;
    const int q0 = blockIdx.x * 128;
    const int kvh = h >> 2;

    const float* Qg = g_q + (((size_t)b * NH + h) * S_LEN + q0) * HD;
    const float* Kg = g_k + (((size_t)b * NKV + kvh) * S_LEN) * HD;
    const float* Vg = g_v + (((size_t)b * NKV + kvh) * S_LEN) * HD;

    for (int idx = tid; idx < 128 * 32; idx += 256) {
        int r = idx >> 5, d4 = (idx & 31) * 4;
        float4 v = *(const float4*)&Qg[r * HD + d4];
        Qs[(d4 + 0) * 129 + r] = v.x;
        Qs[(d4 + 1) * 129 + r] = v.y;
        Qs[(d4 + 2) * 129 + r] = v.z;
        Qs[(d4 + 3) * 129 + r] = v.w;
    }

    float m_r[8], l_r[8], O[8][8];
#pragma unroll
    for (int i = 0; i < 8; i++) {
        m_r[i] = -1e30f;
        l_r[i] = 0.f;
#pragma unroll
        for (int c = 0; c < 8; c++) O[i][c] = 0.f;
    }
    const float scale = 0.08838834764831845f;

    for (int k0 = 0; k0 < S_LEN; k0 += 64) {
        __syncthreads();
        for (int idx = tid; idx < 64 * 32; idx += 256) {
            int c = idx >> 5, d4 = (idx & 31) * 4;
            float4 kv = *(const float4*)&Kg[(k0 + c) * HD + d4];
            Ks[(d4 + 0) * 65 + c] = kv.x;
            Ks[(d4 + 1) * 65 + c] = kv.y;
            Ks[(d4 + 2) * 65 + c] = kv.z;
            Ks[(d4 + 3) * 65 + c] = kv.w;
            float4 vv = *(const float4*)&Vg[(k0 + c) * HD + d4];
            *(float4*)&Vs[c * 128 + d4] = vv;
        }
        __syncthreads();

        float sc[8][4];
#pragma unroll
        for (int i = 0; i < 8; i++)
#pragma unroll
            for (int j = 0; j < 4; j++) sc[i][j] = 0.f;

#pragma unroll 2
        for (int d = 0; d < 128; d++) {
            float qa[8], kb[4];
#pragma unroll
            for (int i = 0; i < 8; i++) qa[i] = Qs[d * 129 + tr * 8 + i];
#pragma unroll
            for (int j = 0; j < 4; j++) kb[j] = Ks[d * 65 + tc * 4 + j];
#pragma unroll
            for (int i = 0; i < 8; i++)
#pragma unroll
                for (int j = 0; j < 4; j++)
                    sc[i][j] = fmaf(qa[i], kb[j], sc[i][j]);
        }
#pragma unroll
        for (int i = 0; i < 8; i++)
#pragma unroll
            for (int j = 0; j < 4; j++) sc[i][j] *= scale;

#pragma unroll
        for (int i = 0; i < 8; i++) {
            float lm = sc[i][0];
            lm = fmaxf(lm, sc[i][1]);
            lm = fmaxf(lm, sc[i][2]);
            lm = fmaxf(lm, sc[i][3]);
            redA[(tr * 8 + i) * 16 + tc] = lm;
        }
        __syncthreads();

        float alpha_r[8];
#pragma unroll
        for (int i = 0; i < 8; i++) {
            int row = tr * 8 + i;
            float mx = m_r[i];
#pragma unroll
            for (int t = 0; t < 16; t++) mx = fmaxf(mx, redA[row * 16 + t]);
            alpha_r[i] = __expf(m_r[i] - mx);
            m_r[i] = mx;
#pragma unroll
            for (int c = 0; c < 8; c++) O[i][c] *= alpha_r[i];
            float ls = 0.f;
#pragma unroll
            for (int j = 0; j < 4; j++) {
                float p = __expf(sc[i][j] - mx);
                ls += p;
                Ps[(tc * 4 + j) * 129 + row] = p;
            }
            redB[row * 16 + tc] = ls;
        }
        __syncthreads();

#pragma unroll
        for (int i = 0; i < 8; i++) {
            int row = tr * 8 + i;
            float rs = 0.f;
#pragma unroll
            for (int t = 0; t < 16; t++) rs += redB[row * 16 + t];
            l_r[i] = l_r[i] * alpha_r[i] + rs;
        }

#pragma unroll 2
        for (int j = 0; j < 64; j++) {
            float pa[8], vb[8];
#pragma unroll
            for (int i = 0; i < 8; i++) pa[i] = Ps[j * 129 + tr * 8 + i];
            *(float4*)&vb[0] = *(const float4*)&Vs[j * 128 + tc * 8];
            *(float4*)&vb[4] = *(const float4*)&Vs[j * 128 + tc * 8 + 4];
#pragma unroll
            for (int i = 0; i < 8; i++)
#pragma unroll
                for (int c = 0; c < 8; c++)
                    O[i][c] = fmaf(pa[i], vb[c], O[i][c]);
        }
    }

#pragma unroll
    for (int i = 0; i < 8; i++) {
        int row = tr * 8 + i;
        float inv = 1.0f / l_r[i];
        float* dst = g_ao + ((size_t)(b * S_LEN + q0 + row)) * HDIM + h * HD + tc * 8;
#pragma unroll
        for (int c = 0; c < 8; c++) dst[c] = O[i][c] * inv;
    }
}

// ---------------------------------------------------------------------------
extern "C" void kernel_launch(void* const* d_in, const int* in_sizes, int n_in,
                              void* d_out, int out_size)
{
    const float* hs = (const float*)d_in[0];
    const float* Wq = (const float*)d_in[1];
    const float* Wk = (const float*)d_in[2];
    const float* Wv = (const float*)d_in[3];
    const float* Wo = (const float*)d_in[4];
    float* out = (float*)d_out;

    float *qp, *kp, *vp, *aop;
    cudaGetSymbolAddress((void**)&qp, g_q);
    cudaGetSymbolAddress((void**)&kp, g_k);
    cudaGetSymbolAddress((void**)&vp, g_v);
    cudaGetSymbolAddress((void**)&aop, g_ao);

    __nv_bfloat16 *hsh, *hsl, *wqh, *wql, *wkh, *wkl, *wvh, *wvl, *woh, *wol, *aoh, *aol;
    cudaGetSymbolAddress((void**)&hsh, g_hs_hi); cudaGetSymbolAddress((void**)&hsl, g_hs_lo);
    cudaGetSymbolAddress((void**)&wqh, g_wq_hi); cudaGetSymbolAddress((void**)&wql, g_wq_lo);
    cudaGetSymbolAddress((void**)&wkh, g_wk_hi); cudaGetSymbolAddress((void**)&wkl, g_wk_lo);
    cudaGetSymbolAddress((void**)&wvh, g_wv_hi); cudaGetSymbolAddress((void**)&wvl, g_wv_lo);
    cudaGetSymbolAddress((void**)&woh, g_wo_hi); cudaGetSymbolAddress((void**)&wol, g_wo_lo);
    cudaGetSymbolAddress((void**)&aoh, g_ao_hi); cudaGetSymbolAddress((void**)&aol, g_ao_lo);

    cudaFuncSetAttribute(flash_kernel, cudaFuncAttributeMaxDynamicSharedMemorySize, SMEM_FLASH);

    // fp32 -> (hi, lo) bf16 splits
    int n4_hs = NB * S_LEN * HDIM / 4;
    int n4_wq = NH * HD * HDIM / 4;
    int n4_wk = NKV * HD * HDIM / 4;
    cvt_kernel<<<(n4_hs + 255) / 256, 256>>>(hs, hsh, hsl, n4_hs);
    cvt_kernel<<<(n4_wq + 255) / 256, 256>>>(Wq, wqh, wql, n4_wq);
    cvt_kernel<<<(n4_wk + 255) / 256, 256>>>(Wk, wkh, wkl, n4_wk);
    cvt_kernel<<<(n4_wk + 255) / 256, 256>>>(Wv, wvh, wvl, n4_wk);
    cvt_kernel<<<(n4_wq + 255) / 256, 256>>>(Wo, woh, wol, n4_wq);

    // QKV projections (HMMA split-bf16) with head-layout scatter
    gemm_mma_kernel<<<dim3(16, 32), 256>>>(hsh, hsl, wqh, wql, qp, NH, 1);
    gemm_mma_kernel<<<dim3(4, 32), 256>>>(hsh, hsl, wkh, wkl, kp, NKV, 1);
    gemm_mma_kernel<<<dim3(4, 32), 256>>>(hsh, hsl, wvh, wvl, vp, NKV, 1);

    // RoPE on q and k
    rope_kernel<<<(NB * NH * S_LEN * 64) / 256, 256>>>(qp, NB * NH * S_LEN * 64);
    rope_kernel<<<(NB * NKV * S_LEN * 64) / 256, 256>>>(kp, NB * NKV * S_LEN * 64);

    // Attention (fp32 flash, unchanged)
    flash_kernel<<<dim3(16, NH, NB), 256, SMEM_FLASH>>>();

    // Output projection (HMMA split-bf16)
    int n4_ao = NB * S_LEN * HDIM / 4;
    cvt_kernel<<<(n4_ao + 255) / 256, 256>>>(aop, aoh, aol, n4_ao);
    gemm_mma_kernel<<<dim3(16, 32), 256>>>(aoh, aol, woh, wol, out, 0, 0);
}

// round 7
// speedup vs baseline: 2.4996x; 1.8443x over previous
#include <cuda_runtime.h>
#include <cuda_bf16.h>
#include <math.h>
#include <stdint.h>

#define S_LEN 2048
#define NB 2
#define NH 16
#define NKV 4
#define HD 128
#define HDIM 2048
#define GK 2048

// ---------------- fp32 scratch ----------------
__device__ float g_q[NB * NH * S_LEN * HD];    // [b][h][s][d]
__device__ float g_k[NB * NKV * S_LEN * HD];
__device__ float g_v[NB * NKV * S_LEN * HD];
__device__ float g_ao[NB * S_LEN * NH * HD];   // [b][s][h*128+d]

// ---------------- bf16 split scratch ----------------
__device__ __nv_bfloat16 g_hs_hi[NB * S_LEN * HDIM], g_hs_lo[NB * S_LEN * HDIM];
__device__ __nv_bfloat16 g_wq_hi[NH * HD * HDIM],    g_wq_lo[NH * HD * HDIM];
__device__ __nv_bfloat16 g_wk_hi[NKV * HD * HDIM],   g_wk_lo[NKV * HD * HDIM];
__device__ __nv_bfloat16 g_wv_hi[NKV * HD * HDIM],   g_wv_lo[NKV * HD * HDIM];
__device__ __nv_bfloat16 g_wo_hi[HDIM * HDIM],       g_wo_lo[HDIM * HDIM];
__device__ __nv_bfloat16 g_ao_hi[NB * S_LEN * HDIM], g_ao_lo[NB * S_LEN * HDIM];
// attention operands (post-rope / transposed)
__device__ __nv_bfloat16 g_qh[NB * NH * S_LEN * HD],  g_ql[NB * NH * S_LEN * HD];
__device__ __nv_bfloat16 g_kh[NB * NKV * S_LEN * HD], g_kl[NB * NKV * S_LEN * HD];
__device__ __nv_bfloat16 g_vth[NB * NKV * HD * S_LEN], g_vtl[NB * NKV * HD * S_LEN]; // [bk][d][s]

// ---------------- HMMA helpers ----------------
__device__ __forceinline__ uint32_t smem_u32(const void* p) {
    uint32_t a;
    asm("{ .reg .u64 t; cvta.to.shared.u64 t, %1; cvt.u32.u64 %0, t; }" : "=r"(a) : "l"(p));
    return a;
}
__device__ __forceinline__ void ldsm4(uint32_t& r0, uint32_t& r1, uint32_t& r2, uint32_t& r3,
                                      uint32_t addr) {
    asm volatile("ldmatrix.sync.aligned.m8n8.x4.shared.b16 {%0,%1,%2,%3}, [%4];"
                 : "=r"(r0), "=r"(r1), "=r"(r2), "=r"(r3) : "r"(addr));
}
__device__ __forceinline__ void ldsm2(uint32_t& r0, uint32_t& r1, uint32_t addr) {
    asm volatile("ldmatrix.sync.aligned.m8n8.x2.shared.b16 {%0,%1}, [%2];"
                 : "=r"(r0), "=r"(r1) : "r"(addr));
}
__device__ __forceinline__ void mma16816(float* c, const uint32_t* a, const uint32_t* b) {
    asm volatile(
        "mma.sync.aligned.m16n8k16.row.col.f32.bf16.bf16.f32 "
        "{%0,%1,%2,%3}, {%4,%5,%6,%7}, {%8,%9}, {%0,%1,%2,%3};"
        : "+f"(c[0]), "+f"(c[1]), "+f"(c[2]), "+f"(c[3])
        : "r"(a[0]), "r"(a[1]), "r"(a[2]), "r"(a[3]), "r"(b[0]), "r"(b[1]));
}

// ---------------- fp32 -> (hi, lo) bf16 split ----------------
__global__ void cvt_kernel(const float* __restrict__ x, __nv_bfloat16* __restrict__ hi,
                           __nv_bfloat16* __restrict__ lo, int n4)
{
    int i = blockIdx.x * 256 + threadIdx.x;
    if (i >= n4) return;
    float4 v = ((const float4*)x)[i];
    float vs[4] = {v.x, v.y, v.z, v.w};
    uint32_t hw[4], lw[4];
#pragma unroll
    for (int j = 0; j < 4; j++) {
        __nv_bfloat16 h = __float2bfloat16(vs[j]);
        float r = vs[j] - __bfloat162float(h);
        __nv_bfloat16 l = __float2bfloat16(r);
        hw[j] = (uint32_t)__bfloat16_as_ushort(h);
        lw[j] = (uint32_t)__bfloat16_as_ushort(l);
    }
    ((uint2*)hi)[i] = make_uint2(hw[0] | (hw[1] << 16), hw[2] | (hw[3] << 16));
    ((uint2*)lo)[i] = make_uint2(lw[0] | (lw[1] << 16), lw[2] | (lw[3] << 16));
}

// ---------------- HMMA split-bf16 NT GEMM (validated round 6) -------------
#define ASTRIDE 40
#define TILE_BF (128 * ASTRIDE)

__global__ __launch_bounds__(256, 2) void gemm_mma_kernel(
    const __nv_bfloat16* __restrict__ Ah, const __nv_bfloat16* __restrict__ Al,
    const __nv_bfloat16* __restrict__ Bh, const __nv_bfloat16* __restrict__ Bl,
    float* __restrict__ C, int Htot, int scatter)
{
    __shared__ __nv_bfloat16 sm[4 * TILE_BF];
    const int tid = threadIdx.x, wid = tid >> 5, lane = tid & 31;
    const int warp_m = wid & 1, warp_n = wid >> 1;
    const int row0 = blockIdx.y * 128, col0 = blockIdx.x * 128;

    float acc[4][4][4];
#pragma unroll
    for (int mi = 0; mi < 4; mi++)
#pragma unroll
        for (int ni = 0; ni < 4; ni++)
#pragma unroll
            for (int q = 0; q < 4; q++) acc[mi][ni][q] = 0.f;

    const int l15 = lane & 15;
    const int a_row = warp_m * 64 + l15;
    const int a_kof = (lane >> 4) * 8;
    const int b_row = warp_n * 32 + (l15 & 7);
    const int b_kof = (l15 >> 3) * 8;
    uint32_t sa_h = smem_u32(sm), sa_l = smem_u32(sm + TILE_BF);
    uint32_t sb_h = smem_u32(sm + 2 * TILE_BF), sb_l = smem_u32(sm + 3 * TILE_BF);

    for (int kc = 0; kc < GK; kc += 32) {
        __syncthreads();
#pragma unroll
        for (int part = 0; part < 4; part++) {
            const __nv_bfloat16* src = (part == 0) ? Ah : (part == 1) ? Al : (part == 2) ? Bh : Bl;
            int rbase = (part < 2) ? row0 : col0;
            __nv_bfloat16* dst = sm + part * TILE_BF;
#pragma unroll
            for (int j = 0; j < 2; j++) {
                int idx = tid * 2 + j;
                int r = idx >> 2, c = idx & 3;
                uint4 v = *(const uint4*)&src[(size_t)(rbase + r) * GK + kc + c * 8];
                *(uint4*)&dst[r * ASTRIDE + c * 8] = v;
            }
        }
        __syncthreads();

#pragma unroll
        for (int ks = 0; ks < 2; ks++) {
            uint32_t bh[4][2], bl[4][2];
#pragma unroll
            for (int ni = 0; ni < 4; ni++) {
                uint32_t off = ((b_row + ni * 8) * ASTRIDE + ks * 16 + b_kof) * 2;
                ldsm2(bh[ni][0], bh[ni][1], sb_h + off);
                ldsm2(bl[ni][0], bl[ni][1], sb_l + off);
            }
#pragma unroll
            for (int mi = 0; mi < 4; mi++) {
                uint32_t ah[4], al[4];
                uint32_t off = ((a_row + mi * 16) * ASTRIDE + ks * 16 + a_kof) * 2;
                ldsm4(ah[0], ah[1], ah[2], ah[3], sa_h + off);
                ldsm4(al[0], al[1], al[2], al[3], sa_l + off);
#pragma unroll
                for (int ni = 0; ni < 4; ni++) {
                    mma16816(acc[mi][ni], ah, bh[ni]);
                    mma16816(acc[mi][ni], al, bh[ni]);
                    mma16816(acc[mi][ni], ah, bl[ni]);
                }
            }
        }
    }

    const int er = warp_m * 64 + (lane >> 2);
    const int ec = warp_n * 32 + (lane & 3) * 2;
    if (scatter) {
        const int h = col0 >> 7;
#pragma unroll
        for (int mi = 0; mi < 4; mi++)
#pragma unroll
            for (int ni = 0; ni < 4; ni++) {
                int cc = ec + ni * 8;
#pragma unroll
                for (int half = 0; half < 2; half++) {
                    int gi = row0 + er + mi * 16 + half * 8;
                    int b = gi >> 11, s = gi & 2047;
                    float* dst = &C[(((size_t)b * Htot + h) * S_LEN + s) * HD + cc];
                    dst[0] = acc[mi][ni][half * 2 + 0];
                    dst[1] = acc[mi][ni][half * 2 + 1];
                }
            }
    } else {
#pragma unroll
        for (int mi = 0; mi < 4; mi++)
#pragma unroll
            for (int ni = 0; ni < 4; ni++) {
                int cc = col0 + ec + ni * 8;
#pragma unroll
                for (int half = 0; half < 2; half++) {
                    int gi = row0 + er + mi * 16 + half * 8;
                    float* dst = &C[(size_t)gi * HDIM + cc];
                    dst[0] = acc[mi][ni][half * 2 + 0];
                    dst[1] = acc[mi][ni][half * 2 + 1];
                }
            }
    }
}

// ---------------- RoPE + split to bf16 hi/lo (scale folded for q) ---------
__global__ void rope_split_kernel(const float* __restrict__ src,
                                  __nv_bfloat16* __restrict__ hi,
                                  __nv_bfloat16* __restrict__ lo,
                                  int total, float scale)
{
    int idx = blockIdx.x * blockDim.x + threadIdx.x;
    if (idx >= total) return;
    int i = idx & 63;
    int r = idx >> 6;
    int s = r & (S_LEN - 1);
    float inv = powf(10000.0f, -(float)i / 64.0f);
    float f = (float)s * inv;
    float sv, cv;
    sincosf(f, &sv, &cv);
    const float* p = src + (size_t)r * HD;
    float x1 = p[i], x2 = p[i + 64];
    float y1 = (x1 * cv - x2 * sv) * scale;
    float y2 = (x2 * cv + x1 * sv) * scale;
    __nv_bfloat16 h1 = __float2bfloat16(y1);
    __nv_bfloat16 h2 = __float2bfloat16(y2);
    size_t o = (size_t)r * HD;
    hi[o + i]      = h1;
    lo[o + i]      = __float2bfloat16(y1 - __bfloat162float(h1));
    hi[o + i + 64] = h2;
    lo[o + i + 64] = __float2bfloat16(y2 - __bfloat162float(h2));
}

// ---------------- V transpose + split: [bk][s][d] -> [bk][d][s] -----------
__global__ void vsplit_kernel()
{
    __shared__ float t[32][33];
    const int bk = blockIdx.z;
    const int s0 = blockIdx.x * 32, d0 = blockIdx.y * 32;
    const int tx = threadIdx.x, ty = threadIdx.y;
    const float* src = g_v + ((size_t)bk * S_LEN + s0) * HD + d0;
#pragma unroll
    for (int j = 0; j < 4; j++) {
        int sl = ty + j * 8;
        t[sl][tx] = src[(size_t)sl * HD + tx];
    }
    __syncthreads();
#pragma unroll
    for (int j = 0; j < 4; j++) {
        int dl = ty + j * 8;
        float v = t[tx][dl];
        size_t o = ((size_t)bk * HD + d0 + dl) * S_LEN + s0 + tx;
        __nv_bfloat16 h = __float2bfloat16(v);
        g_vth[o] = h;
        g_vtl[o] = __float2bfloat16(v - __bfloat162float(h));
    }
}

// ---------------- HMMA flash attention (3-term split, FA2 registers) ------
// smem offsets in bf16 units
#define QSTR 136
#define VSTR 72
#define SQH 0
#define SQL (128 * QSTR)
#define SKH (2 * 128 * QSTR)
#define SKL (2 * 128 * QSTR + 64 * QSTR)
#define SVH (2 * 128 * QSTR + 2 * 64 * QSTR)
#define SVL (SVH + 128 * VSTR)
#define SMEM_FLASH2 ((SVL + 128 * VSTR) * 2)

__global__ __launch_bounds__(256, 1) void flash_mma_kernel()
{
    extern __shared__ __nv_bfloat16 sm2[];
    const int tid = threadIdx.x, wid = tid >> 5, lane = tid & 31;
    const int b = blockIdx.z, h = blockIdx.y, q0 = blockIdx.x * 128;
    const int kvh = h >> 2;

    const __nv_bfloat16* Qh = g_qh + (((size_t)b * NH + h) * S_LEN + q0) * HD;
    const __nv_bfloat16* Ql = g_ql + (((size_t)b * NH + h) * S_LEN + q0) * HD;
    const __nv_bfloat16* Kh = g_kh + ((size_t)b * NKV + kvh) * S_LEN * HD;
    const __nv_bfloat16* Kl = g_kl + ((size_t)b * NKV + kvh) * S_LEN * HD;
    const __nv_bfloat16* Vh = g_vth + ((size_t)b * NKV + kvh) * HD * S_LEN;
    const __nv_bfloat16* Vl = g_vtl + ((size_t)b * NKV + kvh) * HD * S_LEN;

    // Q tiles (once)
#pragma unroll
    for (int j = 0; j < 8; j++) {
        int idx = j * 256 + tid;          // 0..2047
        int r = idx >> 4, c = idx & 15;
        *(uint4*)&sm2[SQH + r * QSTR + c * 8] = *(const uint4*)&Qh[(size_t)r * HD + c * 8];
        *(uint4*)&sm2[SQL + r * QSTR + c * 8] = *(const uint4*)&Ql[(size_t)r * HD + c * 8];
    }

    float oacc[16][4];
#pragma unroll
    for (int ni = 0; ni < 16; ni++)
#pragma unroll
        for (int q = 0; q < 4; q++) oacc[ni][q] = 0.f;
    float m0 = -1e30f, m1 = -1e30f, l0 = 0.f, l1 = 0.f;

    const int l15 = lane & 15;
    uint32_t smb = smem_u32(sm2);
    uint32_t aQh = smb + (SQH + (wid * 16 + l15) * QSTR + (lane >> 4) * 8) * 2;
    uint32_t aQl = smb + (SQL + (wid * 16 + l15) * QSTR + (lane >> 4) * 8) * 2;
    uint32_t bKh = smb + (SKH + (l15 & 7) * QSTR + (l15 >> 3) * 8) * 2;
    uint32_t bKl = smb + (SKL + (l15 & 7) * QSTR + (l15 >> 3) * 8) * 2;
    uint32_t bVh = smb + (SVH + (l15 & 7) * VSTR + (l15 >> 3) * 8) * 2;
    uint32_t bVl = smb + (SVL + (l15 & 7) * VSTR + (l15 >> 3) * 8) * 2;

    for (int kt = 0; kt < 32; kt++) {
        const int k0 = kt * 64;
        __syncthreads();
#pragma unroll
        for (int j = 0; j < 4; j++) {
            int idx = j * 256 + tid;       // 0..1023
            int r = idx >> 4, c = idx & 15;
            *(uint4*)&sm2[SKH + r * QSTR + c * 8] = *(const uint4*)&Kh[(size_t)(k0 + r) * HD + c * 8];
            *(uint4*)&sm2[SKL + r * QSTR + c * 8] = *(const uint4*)&Kl[(size_t)(k0 + r) * HD + c * 8];
            int r2 = idx >> 3, c2 = idx & 7;
            *(uint4*)&sm2[SVH + r2 * VSTR + c2 * 8] = *(const uint4*)&Vh[(size_t)r2 * S_LEN + k0 + c2 * 8];
            *(uint4*)&sm2[SVL + r2 * VSTR + c2 * 8] = *(const uint4*)&Vl[(size_t)r2 * S_LEN + k0 + c2 * 8];
        }
        __syncthreads();

        // ---- scores: 16 rows x 64 keys per warp, 3-term split ----
        float sacc[8][4];
#pragma unroll
        for (int ni = 0; ni < 8; ni++)
#pragma unroll
            for (int q = 0; q < 4; q++) sacc[ni][q] = 0.f;
#pragma unroll
        for (int ks = 0; ks < 8; ks++) {
            uint32_t ah[4], al[4];
            ldsm4(ah[0], ah[1], ah[2], ah[3], aQh + ks * 32);
            ldsm4(al[0], al[1], al[2], al[3], aQl + ks * 32);
#pragma unroll
            for (int ni = 0; ni < 8; ni++) {
                uint32_t bh[2], bl[2];
                ldsm2(bh[0], bh[1], bKh + (ni * 8 * QSTR + ks * 16) * 2);
                ldsm2(bl[0], bl[1], bKl + (ni * 8 * QSTR + ks * 16) * 2);
                mma16816(sacc[ni], ah, bh);
                mma16816(sacc[ni], al, bh);
                mma16816(sacc[ni], ah, bl);
            }
        }

        // ---- online softmax on fragments (base-2; log2e folded into q) ----
        float mx0 = m0, mx1 = m1;
#pragma unroll
        for (int ni = 0; ni < 8; ni++) {
            mx0 = fmaxf(mx0, fmaxf(sacc[ni][0], sacc[ni][1]));
            mx1 = fmaxf(mx1, fmaxf(sacc[ni][2], sacc[ni][3]));
        }
        mx0 = fmaxf(mx0, __shfl_xor_sync(0xFFFFFFFF, mx0, 1));
        mx0 = fmaxf(mx0, __shfl_xor_sync(0xFFFFFFFF, mx0, 2));
        mx1 = fmaxf(mx1, __shfl_xor_sync(0xFFFFFFFF, mx1, 1));
        mx1 = fmaxf(mx1, __shfl_xor_sync(0xFFFFFFFF, mx1, 2));
        float alpha0 = exp2f(m0 - mx0), alpha1 = exp2f(m1 - mx1);
        m0 = mx0; m1 = mx1;

        uint32_t ph[8][2], pl[8][2];
        float rs0 = 0.f, rs1 = 0.f;
#pragma unroll
        for (int ni = 0; ni < 8; ni++) {
            float p0 = exp2f(sacc[ni][0] - m0);
            float p1 = exp2f(sacc[ni][1] - m0);
            float p2 = exp2f(sacc[ni][2] - m1);
            float p3 = exp2f(sacc[ni][3] - m1);
            rs0 += p0 + p1;
            rs1 += p2 + p3;
            __nv_bfloat162 h01 = __floats2bfloat162_rn(p0, p1);
            __nv_bfloat162 h23 = __floats2bfloat162_rn(p2, p3);
            ph[ni][0] = *reinterpret_cast<uint32_t*>(&h01);
            ph[ni][1] = *reinterpret_cast<uint32_t*>(&h23);
            __nv_bfloat162 l01 = __floats2bfloat162_rn(p0 - __bfloat162float(h01.x),
                                                       p1 - __bfloat162float(h01.y));
            __nv_bfloat162 l23 = __floats2bfloat162_rn(p2 - __bfloat162float(h23.x),
                                                       p3 - __bfloat162float(h23.y));
            pl[ni][0] = *reinterpret_cast<uint32_t*>(&l01);
            pl[ni][1] = *reinterpret_cast<uint32_t*>(&l23);
        }
        rs0 += __shfl_xor_sync(0xFFFFFFFF, rs0, 1);
        rs0 += __shfl_xor_sync(0xFFFFFFFF, rs0, 2);
        rs1 += __shfl_xor_sync(0xFFFFFFFF, rs1, 1);
        rs1 += __shfl_xor_sync(0xFFFFFFFF, rs1, 2);
        l0 = l0 * alpha0 + rs0;
        l1 = l1 * alpha1 + rs1;
#pragma unroll
        for (int ni = 0; ni < 16; ni++) {
            oacc[ni][0] *= alpha0; oacc[ni][1] *= alpha0;
            oacc[ni][2] *= alpha1; oacc[ni][3] *= alpha1;
        }

        // ---- PV: O[16 x 128] += P[16 x 64] * V[64 x 128], 3-term ----
#pragma unroll
        for (int ks = 0; ks < 4; ks++) {
            uint32_t Ahf[4] = {ph[2 * ks][0], ph[2 * ks][1], ph[2 * ks + 1][0], ph[2 * ks + 1][1]};
            uint32_t Alf[4] = {pl[2 * ks][0], pl[2 * ks][1], pl[2 * ks + 1][0], pl[2 * ks + 1][1]};
#pragma unroll
            for (int ni = 0; ni < 16; ni++) {
                uint32_t vh[2], vl[2];
                ldsm2(vh[0], vh[1], bVh + (ni * 8 * VSTR + ks * 16) * 2);
                ldsm2(vl[0], vl[1], bVl + (ni * 8 * VSTR + ks * 16) * 2);
                mma16816(oacc[ni], Ahf, vh);
                mma16816(oacc[ni], Ahf, vl);
                mma16816(oacc[ni], Alf, vh);
            }
        }
    }

    // ---- epilogue ----
    float inv0 = 1.0f / l0, inv1 = 1.0f / l1;
    int r0 = q0 + wid * 16 + (lane >> 2);
    float* dst0 = g_ao + ((size_t)(b * S_LEN + r0)) * HDIM + h * HD + (lane & 3) * 2;
    float* dst1 = dst0 + 8 * HDIM;
#pragma unroll
    for (int ni = 0; ni < 16; ni++) {
        *(float2*)&dst0[ni * 8] = make_float2(oacc[ni][0] * inv0, oacc[ni][1] * inv0);
        *(float2*)&dst1[ni * 8] = make_float2(oacc[ni][2] * inv1, oacc[ni][3] * inv1);
    }
}

// ---------------------------------------------------------------------------
extern "C" void kernel_launch(void* const* d_in, const int* in_sizes, int n_in,
                              void* d_out, int out_size)
{
    const float* hs = (const float*)d_in[0];
    const float* Wq = (const float*)d_in[1];
    const float* Wk = (const float*)d_in[2];
    const float* Wv = (const float*)d_in[3];
    const float* Wo = (const float*)d_in[4];
    float* out = (float*)d_out;

    float *qp, *kp, *vp, *aop;
    cudaGetSymbolAddress((void**)&qp, g_q);
    cudaGetSymbolAddress((void**)&kp, g_k);
    cudaGetSymbolAddress((void**)&vp, g_v);
    cudaGetSymbolAddress((void**)&aop, g_ao);

    __nv_bfloat16 *hsh, *hsl, *wqh, *wql, *wkh, *wkl, *wvh, *wvl, *woh, *wol, *aoh, *aol;
    __nv_bfloat16 *qhp, *qlp, *khp, *klp;
    cudaGetSymbolAddress((void**)&hsh, g_hs_hi); cudaGetSymbolAddress((void**)&hsl, g_hs_lo);
    cudaGetSymbolAddress((void**)&wqh, g_wq_hi); cudaGetSymbolAddress((void**)&wql, g_wq_lo);
    cudaGetSymbolAddress((void**)&wkh, g_wk_hi); cudaGetSymbolAddress((void**)&wkl, g_wk_lo);
    cudaGetSymbolAddress((void**)&wvh, g_wv_hi); cudaGetSymbolAddress((void**)&wvl, g_wv_lo);
    cudaGetSymbolAddress((void**)&woh, g_wo_hi); cudaGetSymbolAddress((void**)&wol, g_wo_lo);
    cudaGetSymbolAddress((void**)&aoh, g_ao_hi); cudaGetSymbolAddress((void**)&aol, g_ao_lo);
    cudaGetSymbolAddress((void**)&qhp, g_qh);    cudaGetSymbolAddress((void**)&qlp, g_ql);
    cudaGetSymbolAddress((void**)&khp, g_kh);    cudaGetSymbolAddress((void**)&klp, g_kl);

    cudaFuncSetAttribute(flash_mma_kernel, cudaFuncAttributeMaxDynamicSharedMemorySize, SMEM_FLASH2);

    // fp32 -> (hi, lo) bf16 splits of inputs
    int n4_hs = NB * S_LEN * HDIM / 4;
    int n4_wq = NH * HD * HDIM / 4;
    int n4_wk = NKV * HD * HDIM / 4;
    cvt_kernel<<<(n4_hs + 255) / 256, 256>>>(hs, hsh, hsl, n4_hs);
    cvt_kernel<<<(n4_wq + 255) / 256, 256>>>(Wq, wqh, wql, n4_wq);
    cvt_kernel<<<(n4_wk + 255) / 256, 256>>>(Wk, wkh, wkl, n4_wk);
    cvt_kernel<<<(n4_wk + 255) / 256, 256>>>(Wv, wvh, wvl, n4_wk);
    cvt_kernel<<<(n4_wq + 255) / 256, 256>>>(Wo, woh, wol, n4_wq);

    // QKV projections (HMMA split-bf16) with head-layout scatter
    gemm_mma_kernel<<<dim3(16, 32), 256>>>(hsh, hsl, wqh, wql, qp, NH, 1);
    gemm_mma_kernel<<<dim3(4, 32), 256>>>(hsh, hsl, wkh, wkl, kp, NKV, 1);
    gemm_mma_kernel<<<dim3(4, 32), 256>>>(hsh, hsl, wvh, wvl, vp, NKV, 1);

    // RoPE + split (q carries log2e/sqrt(d)); V transpose + split
    const float QSCALE = 1.4426950408889634f / 11.313708498984760f;
    rope_split_kernel<<<(NB * NH * S_LEN * 64) / 256, 256>>>(qp, qhp, qlp, NB * NH * S_LEN * 64, QSCALE);
    rope_split_kernel<<<(NB * NKV * S_LEN * 64) / 256, 256>>>(kp, khp, klp, NB * NKV * S_LEN * 64, 1.0f);
    vsplit_kernel<<<dim3(S_LEN / 32, HD / 32, NB * NKV), dim3(32, 8)>>>();

    // Attention (HMMA flash)
    flash_mma_kernel<<<dim3(16, NH, NB), 256, SMEM_FLASH2>>>();

    // Output projection (HMMA split-bf16)
    int n4_ao = NB * S_LEN * HDIM / 4;
    cvt_kernel<<<(n4_ao + 255) / 256, 256>>>(aop, aoh, aol, n4_ao);
    gemm_mma_kernel<<<dim3(16, 32), 256>>>(aoh, aol, woh, wol, out, 0, 0);
}

// round 8
// speedup vs baseline: 3.0150x; 1.2062x over previous
#include <cuda_runtime.h>
#include <cuda_bf16.h>
#include <cuda_fp16.h>
#include <math.h>
#include <stdint.h>

#define S_LEN 2048
#define NB 2
#define NH 16
#define NKV 4
#define HD 128
#define HDIM 2048
#define GK 2048

// ---------------- fp32 scratch ----------------
__device__ float g_q[NB * NH * S_LEN * HD];    // [b][h][s][d]
__device__ float g_k[NB * NKV * S_LEN * HD];
__device__ float g_v[NB * NKV * S_LEN * HD];
__device__ float g_ao[NB * S_LEN * NH * HD];   // [b][s][h*128+d]

// ---------------- bf16 split scratch (projections) ----------------
__device__ __nv_bfloat16 g_hs_hi[NB * S_LEN * HDIM], g_hs_lo[NB * S_LEN * HDIM];
__device__ __nv_bfloat16 g_wq_hi[NH * HD * HDIM],    g_wq_lo[NH * HD * HDIM];
__device__ __nv_bfloat16 g_wk_hi[NKV * HD * HDIM],   g_wk_lo[NKV * HD * HDIM];
__device__ __nv_bfloat16 g_wv_hi[NKV * HD * HDIM],   g_wv_lo[NKV * HD * HDIM];
__device__ __nv_bfloat16 g_wo_hi[HDIM * HDIM],       g_wo_lo[HDIM * HDIM];
__device__ __nv_bfloat16 g_ao_hi[NB * S_LEN * HDIM], g_ao_lo[NB * S_LEN * HDIM];

// ---------------- fp16 attention operands ----------------
__device__ __half g_fqh[NB * NH * S_LEN * HD], g_fql[NB * NH * S_LEN * HD];
__device__ __half g_fkh[NB * NKV * S_LEN * HD];          // single fp16
__device__ __half g_fvt[NB * NKV * HD * S_LEN];          // [bk][d][s], single fp16

// ---------------- MMA helpers ----------------
__device__ __forceinline__ uint32_t smem_u32(const void* p) {
    uint32_t a;
    asm("{ .reg .u64 t; cvta.to.shared.u64 t, %1; cvt.u32.u64 %0, t; }" : "=r"(a) : "l"(p));
    return a;
}
__device__ __forceinline__ void ldsm4(uint32_t& r0, uint32_t& r1, uint32_t& r2, uint32_t& r3,
                                      uint32_t addr) {
    asm volatile("ldmatrix.sync.aligned.m8n8.x4.shared.b16 {%0,%1,%2,%3}, [%4];"
                 : "=r"(r0), "=r"(r1), "=r"(r2), "=r"(r3) : "r"(addr));
}
__device__ __forceinline__ void ldsm2(uint32_t& r0, uint32_t& r1, uint32_t addr) {
    asm volatile("ldmatrix.sync.aligned.m8n8.x2.shared.b16 {%0,%1}, [%2];"
                 : "=r"(r0), "=r"(r1) : "r"(addr));
}
__device__ __forceinline__ void mma_bf16(float* c, const uint32_t* a, const uint32_t* b) {
    asm volatile(
        "mma.sync.aligned.m16n8k16.row.col.f32.bf16.bf16.f32 "
        "{%0,%1,%2,%3}, {%4,%5,%6,%7}, {%8,%9}, {%0,%1,%2,%3};"
        : "+f"(c[0]), "+f"(c[1]), "+f"(c[2]), "+f"(c[3])
        : "r"(a[0]), "r"(a[1]), "r"(a[2]), "r"(a[3]), "r"(b[0]), "r"(b[1]));
}
__device__ __forceinline__ void mma_f16(float* c, const uint32_t* a, const uint32_t* b) {
    asm volatile(
        "mma.sync.aligned.m16n8k16.row.col.f32.f16.f16.f32 "
        "{%0,%1,%2,%3}, {%4,%5,%6,%7}, {%8,%9}, {%0,%1,%2,%3};"
        : "+f"(c[0]), "+f"(c[1]), "+f"(c[2]), "+f"(c[3])
        : "r"(a[0]), "r"(a[1]), "r"(a[2]), "r"(a[3]), "r"(b[0]), "r"(b[1]));
}
__device__ __forceinline__ void cp16(uint32_t dst, const void* src) {
    asm volatile("cp.async.cg.shared.global [%0], [%1], 16;" :: "r"(dst), "l"(src));
}
#define CP_COMMIT() asm volatile("cp.async.commit_group;" ::: "memory")
#define CP_WAIT0()  asm volatile("cp.async.wait_group 0;" ::: "memory")

// ---------------- fp32 -> (hi, lo) bf16 split ----------------
__global__ void cvt_kernel(const float* __restrict__ x, __nv_bfloat16* __restrict__ hi,
                           __nv_bfloat16* __restrict__ lo, int n4)
{
    int i = blockIdx.x * 256 + threadIdx.x;
    if (i >= n4) return;
    float4 v = ((const float4*)x)[i];
    float vs[4] = {v.x, v.y, v.z, v.w};
    uint32_t hw[4], lw[4];
#pragma unroll
    for (int j = 0; j < 4; j++) {
        __nv_bfloat16 h = __float2bfloat16(vs[j]);
        float r = vs[j] - __bfloat162float(h);
        __nv_bfloat16 l = __float2bfloat16(r);
        hw[j] = (uint32_t)__bfloat16_as_ushort(h);
        lw[j] = (uint32_t)__bfloat16_as_ushort(l);
    }
    ((uint2*)hi)[i] = make_uint2(hw[0] | (hw[1] << 16), hw[2] | (hw[3] << 16));
    ((uint2*)lo)[i] = make_uint2(lw[0] | (lw[1] << 16), lw[2] | (lw[3] << 16));
}

// ---------------- HMMA split-bf16 NT GEMM core (validated round 6) --------
#define ASTRIDE 40
#define TILE_BF (128 * ASTRIDE)

__device__ __forceinline__ void gemm_body(
    const __nv_bfloat16* __restrict__ Ah, const __nv_bfloat16* __restrict__ Al,
    const __nv_bfloat16* __restrict__ Bh, const __nv_bfloat16* __restrict__ Bl,
    float* __restrict__ C, int Htot, int scatter, int row0, int col0,
    __nv_bfloat16* sm)
{
    const int tid = threadIdx.x, wid = tid >> 5, lane = tid & 31;
    const int warp_m = wid & 1, warp_n = wid >> 1;

    float acc[4][4][4];
#pragma unroll
    for (int mi = 0; mi < 4; mi++)
#pragma unroll
        for (int ni = 0; ni < 4; ni++)
#pragma unroll
            for (int q = 0; q < 4; q++) acc[mi][ni][q] = 0.f;

    const int l15 = lane & 15;
    const int a_row = warp_m * 64 + l15;
    const int a_kof = (lane >> 4) * 8;
    const int b_row = warp_n * 32 + (l15 & 7);
    const int b_kof = (l15 >> 3) * 8;
    uint32_t sa_h = smem_u32(sm), sa_l = smem_u32(sm + TILE_BF);
    uint32_t sb_h = smem_u32(sm + 2 * TILE_BF), sb_l = smem_u32(sm + 3 * TILE_BF);

    for (int kc = 0; kc < GK; kc += 32) {
        __syncthreads();
#pragma unroll
        for (int part = 0; part < 4; part++) {
            const __nv_bfloat16* src = (part == 0) ? Ah : (part == 1) ? Al : (part == 2) ? Bh : Bl;
            int rbase = (part < 2) ? row0 : col0;
            __nv_bfloat16* dst = sm + part * TILE_BF;
#pragma unroll
            for (int j = 0; j < 2; j++) {
                int idx = tid * 2 + j;
                int r = idx >> 2, c = idx & 3;
                uint4 v = *(const uint4*)&src[(size_t)(rbase + r) * GK + kc + c * 8];
                *(uint4*)&dst[r * ASTRIDE + c * 8] = v;
            }
        }
        __syncthreads();

#pragma unroll
        for (int ks = 0; ks < 2; ks++) {
            uint32_t bh[4][2], bl[4][2];
#pragma unroll
            for (int ni = 0; ni < 4; ni++) {
                uint32_t off = ((b_row + ni * 8) * ASTRIDE + ks * 16 + b_kof) * 2;
                ldsm2(bh[ni][0], bh[ni][1], sb_h + off);
                ldsm2(bl[ni][0], bl[ni][1], sb_l + off);
            }
#pragma unroll
            for (int mi = 0; mi < 4; mi++) {
                uint32_t ah[4], al[4];
                uint32_t off = ((a_row + mi * 16) * ASTRIDE + ks * 16 + a_kof) * 2;
                ldsm4(ah[0], ah[1], ah[2], ah[3], sa_h + off);
                ldsm4(al[0], al[1], al[2], al[3], sa_l + off);
#pragma unroll
                for (int ni = 0; ni < 4; ni++) {
                    mma_bf16(acc[mi][ni], ah, bh[ni]);
                    mma_bf16(acc[mi][ni], al, bh[ni]);
                    mma_bf16(acc[mi][ni], ah, bl[ni]);
                }
            }
        }
    }

    const int er = warp_m * 64 + (lane >> 2);
    const int ec = warp_n * 32 + (lane & 3) * 2;
    if (scatter) {
        const int h = col0 >> 7;
#pragma unroll
        for (int mi = 0; mi < 4; mi++)
#pragma unroll
            for (int ni = 0; ni < 4; ni++) {
                int cc = ec + ni * 8;
#pragma unroll
                for (int half = 0; half < 2; half++) {
                    int gi = row0 + er + mi * 16 + half * 8;
                    int b = gi >> 11, s = gi & 2047;
                    float* dst = &C[(((size_t)b * Htot + h) * S_LEN + s) * HD + (cc & 127)];
                    dst[0] = acc[mi][ni][half * 2 + 0];
                    dst[1] = acc[mi][ni][half * 2 + 1];
                }
            }
    } else {
#pragma unroll
        for (int mi = 0; mi < 4; mi++)
#pragma unroll
            for (int ni = 0; ni < 4; ni++) {
                int cc = col0 + ec + ni * 8;
#pragma unroll
                for (int half = 0; half < 2; half++) {
                    int gi = row0 + er + mi * 16 + half * 8;
                    float* dst = &C[(size_t)gi * HDIM + cc];
                    dst[0] = acc[mi][ni][half * 2 + 0];
                    dst[1] = acc[mi][ni][half * 2 + 1];
                }
            }
    }
}

// Fused QKV: blockIdx.x routes to Q (0-15), K (16-19), V (20-23)
__global__ __launch_bounds__(256, 2) void gemm_qkv_kernel()
{
    __shared__ __nv_bfloat16 sm[4 * TILE_BF];
    const int bx = blockIdx.x;
    const int row0 = blockIdx.y * 128;
    if (bx < 16)
        gemm_body(g_hs_hi, g_hs_lo, g_wq_hi, g_wq_lo, g_q, NH, 1, row0, bx * 128, sm);
    else if (bx < 20)
        gemm_body(g_hs_hi, g_hs_lo, g_wk_hi, g_wk_lo, g_k, NKV, 1, row0, (bx - 16) * 128, sm);
    else
        gemm_body(g_hs_hi, g_hs_lo, g_wv_hi, g_wv_lo, g_v, NKV, 1, row0, (bx - 20) * 128, sm);
}

// Generic (O projection)
__global__ __launch_bounds__(256, 2) void gemm_mma_kernel(
    const __nv_bfloat16* __restrict__ Ah, const __nv_bfloat16* __restrict__ Al,
    const __nv_bfloat16* __restrict__ Bh, const __nv_bfloat16* __restrict__ Bl,
    float* __restrict__ C)
{
    __shared__ __nv_bfloat16 sm[4 * TILE_BF];
    gemm_body(Ah, Al, Bh, Bl, C, 0, 0, blockIdx.y * 128, blockIdx.x * 128, sm);
}

// ---------------- RoPE -> fp16 (q: split hi/lo with scale; k: single) -----
__global__ void rope_q_f16(int total, float scale)
{
    int idx = blockIdx.x * blockDim.x + threadIdx.x;
    if (idx >= total) return;
    int i = idx & 63;
    int r = idx >> 6;
    int s = r & (S_LEN - 1);
    float inv = powf(10000.0f, -(float)i / 64.0f);
    float f = (float)s * inv;
    float sv, cv;
    sincosf(f, &sv, &cv);
    const float* p = g_q + (size_t)r * HD;
    float x1 = p[i], x2 = p[i + 64];
    float y1 = (x1 * cv - x2 * sv) * scale;
    float y2 = (x2 * cv + x1 * sv) * scale;
    size_t o = (size_t)r * HD;
    __half h1 = __float2half_rn(y1);
    __half h2 = __float2half_rn(y2);
    g_fqh[o + i] = h1;      g_fql[o + i] = __float2half_rn(y1 - __half2float(h1));
    g_fqh[o + i + 64] = h2; g_fql[o + i + 64] = __float2half_rn(y2 - __half2float(h2));
}

__global__ void rope_k_f16(int total)
{
    int idx = blockIdx.x * blockDim.x + threadIdx.x;
    if (idx >= total) return;
    int i = idx & 63;
    int r = idx >> 6;
    int s = r & (S_LEN - 1);
    float inv = powf(10000.0f, -(float)i / 64.0f);
    float f = (float)s * inv;
    float sv, cv;
    sincosf(f, &sv, &cv);
    const float* p = g_k + (size_t)r * HD;
    float x1 = p[i], x2 = p[i + 64];
    size_t o = (size_t)r * HD;
    g_fkh[o + i]      = __float2half_rn(x1 * cv - x2 * sv);
    g_fkh[o + i + 64] = __float2half_rn(x2 * cv + x1 * sv);
}

// ---------------- V transpose -> fp16: [bk][s][d] -> [bk][d][s] -----------
__global__ void vsplit_f16()
{
    __shared__ float t[32][33];
    const int bk = blockIdx.z;
    const int s0 = blockIdx.x * 32, d0 = blockIdx.y * 32;
    const int tx = threadIdx.x, ty = threadIdx.y;
    const float* src = g_v + ((size_t)bk * S_LEN + s0) * HD + d0;
#pragma unroll
    for (int j = 0; j < 4; j++) {
        int sl = ty + j * 8;
        t[sl][tx] = src[(size_t)sl * HD + tx];
    }
    __syncthreads();
#pragma unroll
    for (int j = 0; j < 4; j++) {
        int dl = ty + j * 8;
        g_fvt[((size_t)bk * HD + d0 + dl) * S_LEN + s0 + tx] = __float2half_rn(t[tx][dl]);
    }
}

// ---------------- fp16 flash attention (split-A 2-term, cp.async) ---------
// smem (halves): Qhi[128][136], Qlo[128][136], 2 stages of { K[64][136], V[128][72] }
#define QSTR 136
#define VSTR 72
#define SQH  0
#define SQL  (128 * QSTR)
#define KVST (64 * QSTR + 128 * VSTR)          // 17920 halves per stage
#define SKV0 (2 * 128 * QSTR)                   // 34816
#define SMEM_FLASH3 ((SKV0 + 2 * KVST) * 2)     // 141312 bytes

__global__ __launch_bounds__(256, 1) void flash_f16_kernel()
{
    extern __shared__ __half smh[];
    const int tid = threadIdx.x, wid = tid >> 5, lane = tid & 31;
    const int b = blockIdx.z, h = blockIdx.y, q0 = blockIdx.x * 128;
    const int kvh = h >> 2;

    const __half* Qh = g_fqh + (((size_t)b * NH + h) * S_LEN + q0) * HD;
    const __half* Ql = g_fql + (((size_t)b * NH + h) * S_LEN + q0) * HD;
    const __half* Kg = g_fkh + ((size_t)b * NKV + kvh) * S_LEN * HD;
    const __half* Vg = g_fvt + ((size_t)b * NKV + kvh) * HD * S_LEN;

    uint32_t smb = smem_u32(smh);

    // async prefetch of tile 0 K/V
    {
        const int st = 0, k0 = 0;
        uint32_t kb = smb + (SKV0 + st * KVST) * 2;
        uint32_t vb = kb + 64 * QSTR * 2;
#pragma unroll
        for (int j = 0; j < 4; j++) {
            int idx = j * 256 + tid;
            int r = idx >> 4, c = idx & 15;
            cp16(kb + (r * QSTR + c * 8) * 2, &Kg[(size_t)(k0 + r) * HD + c * 8]);
            int r2 = idx >> 3, c2 = idx & 7;
            cp16(vb + (r2 * VSTR + c2 * 8) * 2, &Vg[(size_t)r2 * S_LEN + k0 + c2 * 8]);
        }
        CP_COMMIT();
    }

    // Q tiles (sync)
#pragma unroll
    for (int j = 0; j < 8; j++) {
        int idx = j * 256 + tid;
        int r = idx >> 4, c = idx & 15;
        *(uint4*)&smh[SQH + r * QSTR + c * 8] = *(const uint4*)&Qh[(size_t)r * HD + c * 8];
        *(uint4*)&smh[SQL + r * QSTR + c * 8] = *(const uint4*)&Ql[(size_t)r * HD + c * 8];
    }

    float oacc[16][4];
#pragma unroll
    for (int ni = 0; ni < 16; ni++)
#pragma unroll
        for (int q = 0; q < 4; q++) oacc[ni][q] = 0.f;
    float m0 = -1e30f, m1 = -1e30f, l0 = 0.f, l1 = 0.f;

    const int l15 = lane & 15;
    uint32_t aQh = smb + (SQH + (wid * 16 + l15) * QSTR + (lane >> 4) * 8) * 2;
    uint32_t aQl = smb + (SQL + (wid * 16 + l15) * QSTR + (lane >> 4) * 8) * 2;
    uint32_t bKof = ((l15 & 7) * QSTR + (l15 >> 3) * 8) * 2;
    uint32_t bVof = ((l15 & 7) * VSTR + (l15 >> 3) * 8) * 2;

    CP_WAIT0();
    __syncthreads();

    for (int kt = 0; kt < 32; kt++) {
        const int st = kt & 1;
        // prefetch next tile into other stage
        if (kt + 1 < 32) {
            const int k0n = (kt + 1) * 64, stn = st ^ 1;
            uint32_t kb = smb + (SKV0 + stn * KVST) * 2;
            uint32_t vb = kb + 64 * QSTR * 2;
#pragma unroll
            for (int j = 0; j < 4; j++) {
                int idx = j * 256 + tid;
                int r = idx >> 4, c = idx & 15;
                cp16(kb + (r * QSTR + c * 8) * 2, &Kg[(size_t)(k0n + r) * HD + c * 8]);
                int r2 = idx >> 3, c2 = idx & 7;
                cp16(vb + (r2 * VSTR + c2 * 8) * 2, &Vg[(size_t)r2 * S_LEN + k0n + c2 * 8]);
            }
            CP_COMMIT();
        }
        uint32_t bKh = smb + (SKV0 + st * KVST) * 2 + bKof;
        uint32_t bVh = smb + (SKV0 + st * KVST + 64 * QSTR) * 2 + bVof;

        // ---- scores: 16 rows x 64 keys per warp, 2-term (Q split, K single)
        float sacc[8][4];
#pragma unroll
        for (int ni = 0; ni < 8; ni++)
#pragma unroll
            for (int q = 0; q < 4; q++) sacc[ni][q] = 0.f;
#pragma unroll
        for (int ks = 0; ks < 8; ks++) {
            uint32_t ah[4], al[4];
            ldsm4(ah[0], ah[1], ah[2], ah[3], aQh + ks * 32);
            ldsm4(al[0], al[1], al[2], al[3], aQl + ks * 32);
#pragma unroll
            for (int ni = 0; ni < 8; ni++) {
                uint32_t kh[2];
                ldsm2(kh[0], kh[1], bKh + (ni * 8 * QSTR + ks * 16) * 2);
                mma_f16(sacc[ni], ah, kh);
                mma_f16(sacc[ni], al, kh);
            }
        }

        // ---- online softmax (base-2; log2e/sqrt(d) folded into q) ----
        float mx0 = m0, mx1 = m1;
#pragma unroll
        for (int ni = 0; ni < 8; ni++) {
            mx0 = fmaxf(mx0, fmaxf(sacc[ni][0], sacc[ni][1]));
            mx1 = fmaxf(mx1, fmaxf(sacc[ni][2], sacc[ni][3]));
        }
        mx0 = fmaxf(mx0, __shfl_xor_sync(0xFFFFFFFF, mx0, 1));
        mx0 = fmaxf(mx0, __shfl_xor_sync(0xFFFFFFFF, mx0, 2));
        mx1 = fmaxf(mx1, __shfl_xor_sync(0xFFFFFFFF, mx1, 1));
        mx1 = fmaxf(mx1, __shfl_xor_sync(0xFFFFFFFF, mx1, 2));
        float alpha0 = exp2f(m0 - mx0), alpha1 = exp2f(m1 - mx1);
        m0 = mx0; m1 = mx1;

        uint32_t ph[8][2], pl[8][2];
        float rs0 = 0.f, rs1 = 0.f;
#pragma unroll
        for (int ni = 0; ni < 8; ni++) {
            float p0 = exp2f(sacc[ni][0] - m0);
            float p1 = exp2f(sacc[ni][1] - m0);
            float p2 = exp2f(sacc[ni][2] - m1);
            float p3 = exp2f(sacc[ni][3] - m1);
            rs0 += p0 + p1;
            rs1 += p2 + p3;
            __half2 h01 = __floats2half2_rn(p0, p1);
            __half2 h23 = __floats2half2_rn(p2, p3);
            ph[ni][0] = *reinterpret_cast<uint32_t*>(&h01);
            ph[ni][1] = *reinterpret_cast<uint32_t*>(&h23);
            __half2 l01 = __floats2half2_rn(p0 - __half2float(__low2half(h01)),
                                            p1 - __half2float(__high2half(h01)));
            __half2 l23 = __floats2half2_rn(p2 - __half2float(__low2half(h23)),
                                            p3 - __half2float(__high2half(h23)));
            pl[ni][0] = *reinterpret_cast<uint32_t*>(&l01);
            pl[ni][1] = *reinterpret_cast<uint32_t*>(&l23);
        }
        rs0 += __shfl_xor_sync(0xFFFFFFFF, rs0, 1);
        rs0 += __shfl_xor_sync(0xFFFFFFFF, rs0, 2);
        rs1 += __shfl_xor_sync(0xFFFFFFFF, rs1, 1);
        rs1 += __shfl_xor_sync(0xFFFFFFFF, rs1, 2);
        l0 = l0 * alpha0 + rs0;
        l1 = l1 * alpha1 + rs1;
#pragma unroll
        for (int ni = 0; ni < 16; ni++) {
            oacc[ni][0] *= alpha0; oacc[ni][1] *= alpha0;
            oacc[ni][2] *= alpha1; oacc[ni][3] *= alpha1;
        }

        // ---- PV: O += (Phi + Plo) * V, V single fp16 ----
#pragma unroll
        for (int ks = 0; ks < 4; ks++) {
            uint32_t Ahf[4] = {ph[2 * ks][0], ph[2 * ks][1], ph[2 * ks + 1][0], ph[2 * ks + 1][1]};
            uint32_t Alf[4] = {pl[2 * ks][0], pl[2 * ks][1], pl[2 * ks + 1][0], pl[2 * ks + 1][1]};
#pragma unroll
            for (int ni = 0; ni < 16; ni++) {
                uint32_t vh[2];
                ldsm2(vh[0], vh[1], bVh + (ni * 8 * VSTR + ks * 16) * 2);
                mma_f16(oacc[ni], Ahf, vh);
                mma_f16(oacc[ni], Alf, vh);
            }
        }

        CP_WAIT0();
        __syncthreads();
    }

    // ---- epilogue ----
    float inv0 = 1.0f / l0, inv1 = 1.0f / l1;
    int r0 = q0 + wid * 16 + (lane >> 2);
    float* dst0 = g_ao + ((size_t)(b * S_LEN + r0)) * HDIM + h * HD + (lane & 3) * 2;
    float* dst1 = dst0 + 8 * HDIM;
#pragma unroll
    for (int ni = 0; ni < 16; ni++) {
        *(float2*)&dst0[ni * 8] = make_float2(oacc[ni][0] * inv0, oacc[ni][1] * inv0);
        *(float2*)&dst1[ni * 8] = make_float2(oacc[ni][2] * inv1, oacc[ni][3] * inv1);
    }
}

// ---------------------------------------------------------------------------
extern "C" void kernel_launch(void* const* d_in, const int* in_sizes, int n_in,
                              void* d_out, int out_size)
{
    const float* hs = (const float*)d_in[0];
    const float* Wq = (const float*)d_in[1];
    const float* Wk = (const float*)d_in[2];
    const float* Wv = (const float*)d_in[3];
    const float* Wo = (const float*)d_in[4];
    float* out = (float*)d_out;

    float *aop;
    cudaGetSymbolAddress((void**)&aop, g_ao);

    __nv_bfloat16 *hsh, *hsl, *wqh, *wql, *wkh, *wkl, *wvh, *wvl, *woh, *wol, *aoh, *aol;
    cudaGetSymbolAddress((void**)&hsh, g_hs_hi); cudaGetSymbolAddress((void**)&hsl, g_hs_lo);
    cudaGetSymbolAddress((void**)&wqh, g_wq_hi); cudaGetSymbolAddress((void**)&wql, g_wq_lo);
    cudaGetSymbolAddress((void**)&wkh, g_wk_hi); cudaGetSymbolAddress((void**)&wkl, g_wk_lo);
    cudaGetSymbolAddress((void**)&wvh, g_wv_hi); cudaGetSymbolAddress((void**)&wvl, g_wv_lo);
    cudaGetSymbolAddress((void**)&woh, g_wo_hi); cudaGetSymbolAddress((void**)&wol, g_wo_lo);
    cudaGetSymbolAddress((void**)&aoh, g_ao_hi); cudaGetSymbolAddress((void**)&aol, g_ao_lo);

    cudaFuncSetAttribute(flash_f16_kernel, cudaFuncAttributeMaxDynamicSharedMemorySize, SMEM_FLASH3);

    // fp32 -> (hi, lo) bf16 splits of inputs
    int n4_hs = NB * S_LEN * HDIM / 4;
    int n4_wq = NH * HD * HDIM / 4;
    int n4_wk = NKV * HD * HDIM / 4;
    cvt_kernel<<<(n4_hs + 255) / 256, 256>>>(hs, hsh, hsl, n4_hs);
    cvt_kernel<<<(n4_wq + 255) / 256, 256>>>(Wq, wqh, wql, n4_wq);
    cvt_kernel<<<(n4_wk + 255) / 256, 256>>>(Wk, wkh, wkl, n4_wk);
    cvt_kernel<<<(n4_wk + 255) / 256, 256>>>(Wv, wvh, wvl, n4_wk);
    cvt_kernel<<<(n4_wq + 255) / 256, 256>>>(Wo, woh, wol, n4_wq);

    // Fused QKV projections (bf16 3-term HMMA) with head-layout scatter
    gemm_qkv_kernel<<<dim3(24, 32), 256>>>();

    // RoPE -> fp16 (q split + folded scale; k single); V transpose -> fp16
    const float QSCALE = 1.4426950408889634f / 11.313708498984760f; // log2e/sqrt(128)
    rope_q_f16<<<(NB * NH * S_LEN * 64) / 256, 256>>>(NB * NH * S_LEN * 64, QSCALE);
    rope_k_f16<<<(NB * NKV * S_LEN * 64) / 256, 256>>>(NB * NKV * S_LEN * 64);
    vsplit_f16<<<dim3(S_LEN / 32, HD / 32, NB * NKV), dim3(32, 8)>>>();

    // Attention (fp16 flash, 2-term, double-buffered cp.async)
    flash_f16_kernel<<<dim3(16, NH, NB), 256, SMEM_FLASH3>>>();

    // Output projection (bf16 3-term HMMA)
    int n4_ao = NB * S_LEN * HDIM / 4;
    cvt_kernel<<<(n4_ao + 255) / 256, 256>>>(aop, aoh, aol, n4_ao);
    gemm_mma_kernel<<<dim3(16, 32), 256>>>(aoh, aol, woh, wol, out);
}

// round 9
// speedup vs baseline: 3.9220x; 1.3008x over previous
#include <cuda_runtime.h>
#include <cuda_fp16.h>
#include <math.h>
#include <stdint.h>

#define S_LEN 2048
#define NB 2
#define NH 16
#define NKV 4
#define HD 128
#define HDIM 2048
#define GK 2048

// ---------------- fp32 scratch ----------------
__device__ float g_q[NB * NH * S_LEN * HD];    // [b][h][s][d]
__device__ float g_k[NB * NKV * S_LEN * HD];
__device__ float g_v[NB * NKV * S_LEN * HD];
__device__ float g_ao[NB * S_LEN * NH * HD];   // [b][s][h*128+d]

// ---------------- fp16 operands ----------------
__device__ __align__(16) __half g_fhsh[NB * S_LEN * HDIM], g_fhsl[NB * S_LEN * HDIM];
__device__ __align__(16) __half g_fwq[NH * HD * HDIM];
__device__ __align__(16) __half g_fwk[NKV * HD * HDIM];
__device__ __align__(16) __half g_fwv[NKV * HD * HDIM];
__device__ __align__(16) __half g_fwo[HDIM * HDIM];
__device__ __align__(16) __half g_faoh[NB * S_LEN * HDIM], g_faol[NB * S_LEN * HDIM];
// attention operands
__device__ __align__(16) __half g_fqh[NB * NH * S_LEN * HD], g_fql[NB * NH * S_LEN * HD];
__device__ __align__(16) __half g_fkh[NB * NKV * S_LEN * HD];
__device__ __align__(16) __half g_fvt[NB * NKV * HD * S_LEN];   // [bk][d][s]

// ---------------- MMA / async helpers ----------------
__device__ __forceinline__ uint32_t smem_u32(const void* p) {
    uint32_t a;
    asm("{ .reg .u64 t; cvta.to.shared.u64 t, %1; cvt.u32.u64 %0, t; }" : "=r"(a) : "l"(p));
    return a;
}
__device__ __forceinline__ void ldsm4(uint32_t& r0, uint32_t& r1, uint32_t& r2, uint32_t& r3,
                                      uint32_t addr) {
    asm volatile("ldmatrix.sync.aligned.m8n8.x4.shared.b16 {%0,%1,%2,%3}, [%4];"
                 : "=r"(r0), "=r"(r1), "=r"(r2), "=r"(r3) : "r"(addr));
}
__device__ __forceinline__ void ldsm2(uint32_t& r0, uint32_t& r1, uint32_t addr) {
    asm volatile("ldmatrix.sync.aligned.m8n8.x2.shared.b16 {%0,%1}, [%2];"
                 : "=r"(r0), "=r"(r1) : "r"(addr));
}
__device__ __forceinline__ void mma_f16(float* c, const uint32_t* a, const uint32_t* b) {
    asm volatile(
        "mma.sync.aligned.m16n8k16.row.col.f32.f16.f16.f32 "
        "{%0,%1,%2,%3}, {%4,%5,%6,%7}, {%8,%9}, {%0,%1,%2,%3};"
        : "+f"(c[0]), "+f"(c[1]), "+f"(c[2]), "+f"(c[3])
        : "r"(a[0]), "r"(a[1]), "r"(a[2]), "r"(a[3]), "r"(b[0]), "r"(b[1]));
}
__device__ __forceinline__ void cp16(uint32_t dst, const void* src) {
    asm volatile("cp.async.cg.shared.global [%0], [%1], 16;" :: "r"(dst), "l"(src));
}
#define CP_COMMIT() asm volatile("cp.async.commit_group;" ::: "memory")
#define CP_WAIT0()  asm volatile("cp.async.wait_group 0;" ::: "memory")
#define CP_WAIT1()  asm volatile("cp.async.wait_group 1;" ::: "memory")

// ---------------- fp32 -> fp16 conversions ----------------
__global__ void cvt_f16s(const float* __restrict__ x, __half* __restrict__ hi,
                         __half* __restrict__ lo, int n4)
{
    int i = blockIdx.x * 256 + threadIdx.x;
    if (i >= n4) return;
    float4 v = ((const float4*)x)[i];
    float vs[4] = {v.x, v.y, v.z, v.w};
    uint32_t hw[4], lw[4];
#pragma unroll
    for (int j = 0; j < 4; j++) {
        __half h = __float2half_rn(vs[j]);
        __half l = __float2half_rn(vs[j] - __half2float(h));
        hw[j] = (uint32_t)__half_as_ushort(h);
        lw[j] = (uint32_t)__half_as_ushort(l);
    }
    ((uint2*)hi)[i] = make_uint2(hw[0] | (hw[1] << 16), hw[2] | (hw[3] << 16));
    ((uint2*)lo)[i] = make_uint2(lw[0] | (lw[1] << 16), lw[2] | (lw[3] << 16));
}

__global__ void cvt_f16(const float* __restrict__ x, __half* __restrict__ y, int n4)
{
    int i = blockIdx.x * 256 + threadIdx.x;
    if (i >= n4) return;
    float4 v = ((const float4*)x)[i];
    uint32_t w[4] = {(uint32_t)__half_as_ushort(__float2half_rn(v.x)),
                     (uint32_t)__half_as_ushort(__float2half_rn(v.y)),
                     (uint32_t)__half_as_ushort(__float2half_rn(v.z)),
                     (uint32_t)__half_as_ushort(__float2half_rn(v.w))};
    ((uint2*)y)[i] = make_uint2(w[0] | (w[1] << 16), w[2] | (w[3] << 16));
}

// ---------------- fp16 2-term NT GEMM with cp.async pipeline --------------
// C[M,N] = (Ah+Al)[M,K] * B[N,K]^T, fp32 accum. Tile 128x128, BK=32, 2-stage.
#define FSTR 40
#define FTILE (128 * FSTR)                   // halves per part
#define GSTG (3 * FTILE)                     // halves per stage (Ah|Al|B)
#define SMEM_GEMM (2 * GSTG * 2)             // bytes = 61440

__device__ __forceinline__ void gemm_issue(
    uint32_t sb0, int stage, int tid,
    const __half* __restrict__ Ah, const __half* __restrict__ Al,
    const __half* __restrict__ B, int row0, int col0, int kc)
{
    uint32_t base = sb0 + stage * GSTG * 2;
#pragma unroll
    for (int part = 0; part < 3; part++) {
        const __half* src = (part == 0) ? Ah : (part == 1) ? Al : B;
        int rbase = (part < 2) ? row0 : col0;
        uint32_t pdst = base + part * FTILE * 2;
#pragma unroll
        for (int j = 0; j < 2; j++) {
            int idx = tid * 2 + j;               // 0..511
            int r = idx >> 2, c = idx & 3;
            cp16(pdst + (r * FSTR + c * 8) * 2,
                 &src[(size_t)(rbase + r) * GK + kc + c * 8]);
        }
    }
}

__device__ __forceinline__ void gemm_body_f16(
    const __half* __restrict__ Ah, const __half* __restrict__ Al,
    const __half* __restrict__ B, float* __restrict__ C,
    int Htot, int scatter, int row0, int col0, __half* gsm)
{
    const int tid = threadIdx.x, wid = tid >> 5, lane = tid & 31;
    const int warp_m = wid & 1, warp_n = wid >> 1;

    float acc[4][4][4];
#pragma unroll
    for (int mi = 0; mi < 4; mi++)
#pragma unroll
        for (int ni = 0; ni < 4; ni++)
#pragma unroll
            for (int q = 0; q < 4; q++) acc[mi][ni][q] = 0.f;

    const int l15 = lane & 15;
    const int a_row = warp_m * 64 + l15;
    const int a_kof = (lane >> 4) * 8;
    const int b_row = warp_n * 32 + (l15 & 7);
    const int b_kof = (l15 >> 3) * 8;
    uint32_t sb0 = smem_u32(gsm);

    gemm_issue(sb0, 0, tid, Ah, Al, B, row0, col0, 0);
    CP_COMMIT();

    for (int c = 0; c < 64; c++) {
        if (c + 1 < 64) {
            gemm_issue(sb0, (c + 1) & 1, tid, Ah, Al, B, row0, col0, (c + 1) * 32);
            CP_COMMIT();
            CP_WAIT1();
        } else {
            CP_WAIT0();
        }
        __syncthreads();

        uint32_t stg = sb0 + (c & 1) * GSTG * 2;
        uint32_t sa_h = stg, sa_l = stg + FTILE * 2, sb_b = stg + 2 * FTILE * 2;
#pragma unroll
        for (int ks = 0; ks < 2; ks++) {
            uint32_t bb[4][2];
#pragma unroll
            for (int ni = 0; ni < 4; ni++) {
                uint32_t off = ((b_row + ni * 8) * FSTR + ks * 16 + b_kof) * 2;
                ldsm2(bb[ni][0], bb[ni][1], sb_b + off);
            }
#pragma unroll
            for (int mi = 0; mi < 4; mi++) {
                uint32_t ah[4], al[4];
                uint32_t off = ((a_row + mi * 16) * FSTR + ks * 16 + a_kof) * 2;
                ldsm4(ah[0], ah[1], ah[2], ah[3], sa_h + off);
                ldsm4(al[0], al[1], al[2], al[3], sa_l + off);
#pragma unroll
                for (int ni = 0; ni < 4; ni++) {
                    mma_f16(acc[mi][ni], ah, bb[ni]);
                    mma_f16(acc[mi][ni], al, bb[ni]);
                }
            }
        }
        __syncthreads();
    }

    const int er = warp_m * 64 + (lane >> 2);
    const int ec = warp_n * 32 + (lane & 3) * 2;
    if (scatter) {
        const int h = col0 >> 7;
#pragma unroll
        for (int mi = 0; mi < 4; mi++)
#pragma unroll
            for (int ni = 0; ni < 4; ni++) {
                int cc = ec + ni * 8;
#pragma unroll
                for (int half = 0; half < 2; half++) {
                    int gi = row0 + er + mi * 16 + half * 8;
                    int b = gi >> 11, s = gi & 2047;
                    float* dst = &C[(((size_t)b * Htot + h) * S_LEN + s) * HD + cc];
                    dst[0] = acc[mi][ni][half * 2 + 0];
                    dst[1] = acc[mi][ni][half * 2 + 1];
                }
            }
    } else {
#pragma unroll
        for (int mi = 0; mi < 4; mi++)
#pragma unroll
            for (int ni = 0; ni < 4; ni++) {
                int cc = col0 + ec + ni * 8;
#pragma unroll
                for (int half = 0; half < 2; half++) {
                    int gi = row0 + er + mi * 16 + half * 8;
                    float* dst = &C[(size_t)gi * HDIM + cc];
                    dst[0] = acc[mi][ni][half * 2 + 0];
                    dst[1] = acc[mi][ni][half * 2 + 1];
                }
            }
    }
}

// Fused QKV: blockIdx.x routes to Q (0-15), K (16-19), V (20-23)
__global__ __launch_bounds__(256, 2) void gemm_qkv_kernel()
{
    extern __shared__ __half gsm[];
    const int bx = blockIdx.x;
    const int row0 = blockIdx.y * 128;
    if (bx < 16)
        gemm_body_f16(g_fhsh, g_fhsl, g_fwq, g_q, NH, 1, row0, bx * 128, gsm);
    else if (bx < 20)
        gemm_body_f16(g_fhsh, g_fhsl, g_fwk, g_k, NKV, 1, row0, (bx - 16) * 128, gsm);
    else
        gemm_body_f16(g_fhsh, g_fhsl, g_fwv, g_v, NKV, 1, row0, (bx - 20) * 128, gsm);
}

// O projection
__global__ __launch_bounds__(256, 2) void gemm_o_kernel(float* __restrict__ out)
{
    extern __shared__ __half gsm[];
    gemm_body_f16(g_faoh, g_faol, g_fwo, out, 0, 0, blockIdx.y * 128, blockIdx.x * 128, gsm);
}

// ---------------- RoPE -> fp16 (q: split hi/lo with scale; k: single) -----
__global__ void rope_q_f16(int total, float scale)
{
    int idx = blockIdx.x * blockDim.x + threadIdx.x;
    if (idx >= total) return;
    int i = idx & 63;
    int r = idx >> 6;
    int s = r & (S_LEN - 1);
    float inv = powf(10000.0f, -(float)i / 64.0f);
    float f = (float)s * inv;
    float sv, cv;
    sincosf(f, &sv, &cv);
    const float* p = g_q + (size_t)r * HD;
    float x1 = p[i], x2 = p[i + 64];
    float y1 = (x1 * cv - x2 * sv) * scale;
    float y2 = (x2 * cv + x1 * sv) * scale;
    size_t o = (size_t)r * HD;
    __half h1 = __float2half_rn(y1);
    __half h2 = __float2half_rn(y2);
    g_fqh[o + i] = h1;      g_fql[o + i] = __float2half_rn(y1 - __half2float(h1));
    g_fqh[o + i + 64] = h2; g_fql[o + i + 64] = __float2half_rn(y2 - __half2float(h2));
}

__global__ void rope_k_f16(int total)
{
    int idx = blockIdx.x * blockDim.x + threadIdx.x;
    if (idx >= total) return;
    int i = idx & 63;
    int r = idx >> 6;
    int s = r & (S_LEN - 1);
    float inv = powf(10000.0f, -(float)i / 64.0f);
    float f = (float)s * inv;
    float sv, cv;
    sincosf(f, &sv, &cv);
    const float* p = g_k + (size_t)r * HD;
    float x1 = p[i], x2 = p[i + 64];
    size_t o = (size_t)r * HD;
    g_fkh[o + i]      = __float2half_rn(x1 * cv - x2 * sv);
    g_fkh[o + i + 64] = __float2half_rn(x2 * cv + x1 * sv);
}

// ---------------- V transpose -> fp16: [bk][s][d] -> [bk][d][s] -----------
__global__ void vsplit_f16()
{
    __shared__ float t[32][33];
    const int bk = blockIdx.z;
    const int s0 = blockIdx.x * 32, d0 = blockIdx.y * 32;
    const int tx = threadIdx.x, ty = threadIdx.y;
    const float* src = g_v + ((size_t)bk * S_LEN + s0) * HD + d0;
#pragma unroll
    for (int j = 0; j < 4; j++) {
        int sl = ty + j * 8;
        t[sl][tx] = src[(size_t)sl * HD + tx];
    }
    __syncthreads();
#pragma unroll
    for (int j = 0; j < 4; j++) {
        int dl = ty + j * 8;
        g_fvt[((size_t)bk * HD + d0 + dl) * S_LEN + s0 + tx] = __float2half_rn(t[tx][dl]);
    }
}

// ---------------- fp16 flash attention (validated round 8) ----------------
#define QSTR 136
#define VSTR 72
#define SQH  0
#define SQL  (128 * QSTR)
#define KVST (64 * QSTR + 128 * VSTR)
#define SKV0 (2 * 128 * QSTR)
#define SMEM_FLASH3 ((SKV0 + 2 * KVST) * 2)

__global__ __launch_bounds__(256, 1) void flash_f16_kernel()
{
    extern __shared__ __half smh[];
    const int tid = threadIdx.x, wid = tid >> 5, lane = tid & 31;
    const int b = blockIdx.z, h = blockIdx.y, q0 = blockIdx.x * 128;
    const int kvh = h >> 2;

    const __half* Qh = g_fqh + (((size_t)b * NH + h) * S_LEN + q0) * HD;
    const __half* Ql = g_fql + (((size_t)b * NH + h) * S_LEN + q0) * HD;
    const __half* Kg = g_fkh + ((size_t)b * NKV + kvh) * S_LEN * HD;
    const __half* Vg = g_fvt + ((size_t)b * NKV + kvh) * HD * S_LEN;

    uint32_t smb = smem_u32(smh);

    {
        uint32_t kb = smb + SKV0 * 2;
        uint32_t vb = kb + 64 * QSTR * 2;
#pragma unroll
        for (int j = 0; j < 4; j++) {
            int idx = j * 256 + tid;
            int r = idx >> 4, c = idx & 15;
            cp16(kb + (r * QSTR + c * 8) * 2, &Kg[(size_t)r * HD + c * 8]);
            int r2 = idx >> 3, c2 = idx & 7;
            cp16(vb + (r2 * VSTR + c2 * 8) * 2, &Vg[(size_t)r2 * S_LEN + c2 * 8]);
        }
        CP_COMMIT();
    }

#pragma unroll
    for (int j = 0; j < 8; j++) {
        int idx = j * 256 + tid;
        int r = idx >> 4, c = idx & 15;
        *(uint4*)&smh[SQH + r * QSTR + c * 8] = *(const uint4*)&Qh[(size_t)r * HD + c * 8];
        *(uint4*)&smh[SQL + r * QSTR + c * 8] = *(const uint4*)&Ql[(size_t)r * HD + c * 8];
    }

    float oacc[16][4];
#pragma unroll
    for (int ni = 0; ni < 16; ni++)
#pragma unroll
        for (int q = 0; q < 4; q++) oacc[ni][q] = 0.f;
    float m0 = -1e30f, m1 = -1e30f, l0 = 0.f, l1 = 0.f;

    const int l15 = lane & 15;
    uint32_t aQh = smb + (SQH + (wid * 16 + l15) * QSTR + (lane >> 4) * 8) * 2;
    uint32_t aQl = smb + (SQL + (wid * 16 + l15) * QSTR + (lane >> 4) * 8) * 2;
    uint32_t bKof = ((l15 & 7) * QSTR + (l15 >> 3) * 8) * 2;
    uint32_t bVof = ((l15 & 7) * VSTR + (l15 >> 3) * 8) * 2;

    CP_WAIT0();
    __syncthreads();

    for (int kt = 0; kt < 32; kt++) {
        const int st = kt & 1;
        if (kt + 1 < 32) {
            const int k0n = (kt + 1) * 64, stn = st ^ 1;
            uint32_t kb = smb + (SKV0 + stn * KVST) * 2;
            uint32_t vb = kb + 64 * QSTR * 2;
#pragma unroll
            for (int j = 0; j < 4; j++) {
                int idx = j * 256 + tid;
                int r = idx >> 4, c = idx & 15;
                cp16(kb + (r * QSTR + c * 8) * 2, &Kg[(size_t)(k0n + r) * HD + c * 8]);
                int r2 = idx >> 3, c2 = idx & 7;
                cp16(vb + (r2 * VSTR + c2 * 8) * 2, &Vg[(size_t)r2 * S_LEN + k0n + c2 * 8]);
            }
            CP_COMMIT();
        }
        uint32_t bKh = smb + (SKV0 + st * KVST) * 2 + bKof;
        uint32_t bVh = smb + (SKV0 + st * KVST + 64 * QSTR) * 2 + bVof;

        float sacc[8][4];
#pragma unroll
        for (int ni = 0; ni < 8; ni++)
#pragma unroll
            for (int q = 0; q < 4; q++) sacc[ni][q] = 0.f;
#pragma unroll
        for (int ks = 0; ks < 8; ks++) {
            uint32_t ah[4], al[4];
            ldsm4(ah[0], ah[1], ah[2], ah[3], aQh + ks * 32);
            ldsm4(al[0], al[1], al[2], al[3], aQl + ks * 32);
#pragma unroll
            for (int ni = 0; ni < 8; ni++) {
                uint32_t kh[2];
                ldsm2(kh[0], kh[1], bKh + (ni * 8 * QSTR + ks * 16) * 2);
                mma_f16(sacc[ni], ah, kh);
                mma_f16(sacc[ni], al, kh);
            }
        }

        float mx0 = m0, mx1 = m1;
#pragma unroll
        for (int ni = 0; ni < 8; ni++) {
            mx0 = fmaxf(mx0, fmaxf(sacc[ni][0], sacc[ni][1]));
            mx1 = fmaxf(mx1, fmaxf(sacc[ni][2], sacc[ni][3]));
        }
        mx0 = fmaxf(mx0, __shfl_xor_sync(0xFFFFFFFF, mx0, 1));
        mx0 = fmaxf(mx0, __shfl_xor_sync(0xFFFFFFFF, mx0, 2));
        mx1 = fmaxf(mx1, __shfl_xor_sync(0xFFFFFFFF, mx1, 1));
        mx1 = fmaxf(mx1, __shfl_xor_sync(0xFFFFFFFF, mx1, 2));
        float alpha0 = exp2f(m0 - mx0), alpha1 = exp2f(m1 - mx1);
        m0 = mx0; m1 = mx1;

        uint32_t ph[8][2], pl[8][2];
        float rs0 = 0.f, rs1 = 0.f;
#pragma unroll
        for (int ni = 0; ni < 8; ni++) {
            float p0 = exp2f(sacc[ni][0] - m0);
            float p1 = exp2f(sacc[ni][1] - m0);
            float p2 = exp2f(sacc[ni][2] - m1);
            float p3 = exp2f(sacc[ni][3] - m1);
            rs0 += p0 + p1;
            rs1 += p2 + p3;
            __half2 h01 = __floats2half2_rn(p0, p1);
            __half2 h23 = __floats2half2_rn(p2, p3);
            ph[ni][0] = *reinterpret_cast<uint32_t*>(&h01);
            ph[ni][1] = *reinterpret_cast<uint32_t*>(&h23);
            __half2 l01 = __floats2half2_rn(p0 - __half2float(__low2half(h01)),
                                            p1 - __half2float(__high2half(h01)));
            __half2 l23 = __floats2half2_rn(p2 - __half2float(__low2half(h23)),
                                            p3 - __half2float(__high2half(h23)));
            pl[ni][0] = *reinterpret_cast<uint32_t*>(&l01);
            pl[ni][1] = *reinterpret_cast<uint32_t*>(&l23);
        }
        rs0 += __shfl_xor_sync(0xFFFFFFFF, rs0, 1);
        rs0 += __shfl_xor_sync(0xFFFFFFFF, rs0, 2);
        rs1 += __shfl_xor_sync(0xFFFFFFFF, rs1, 1);
        rs1 += __shfl_xor_sync(0xFFFFFFFF, rs1, 2);
        l0 = l0 * alpha0 + rs0;
        l1 = l1 * alpha1 + rs1;
#pragma unroll
        for (int ni = 0; ni < 16; ni++) {
            oacc[ni][0] *= alpha0; oacc[ni][1] *= alpha0;
            oacc[ni][2] *= alpha1; oacc[ni][3] *= alpha1;
        }

#pragma unroll
        for (int ks = 0; ks < 4; ks++) {
            uint32_t Ahf[4] = {ph[2 * ks][0], ph[2 * ks][1], ph[2 * ks + 1][0], ph[2 * ks + 1][1]};
            uint32_t Alf[4] = {pl[2 * ks][0], pl[2 * ks][1], pl[2 * ks + 1][0], pl[2 * ks + 1][1]};
#pragma unroll
            for (int ni = 0; ni < 16; ni++) {
                uint32_t vh[2];
                ldsm2(vh[0], vh[1], bVh + (ni * 8 * VSTR + ks * 16) * 2);
                mma_f16(oacc[ni], Ahf, vh);
                mma_f16(oacc[ni], Alf, vh);
            }
        }

        CP_WAIT0();
        __syncthreads();
    }

    float inv0 = 1.0f / l0, inv1 = 1.0f / l1;
    int r0 = q0 + wid * 16 + (lane >> 2);
    float* dst0 = g_ao + ((size_t)(b * S_LEN + r0)) * HDIM + h * HD + (lane & 3) * 2;
    float* dst1 = dst0 + 8 * HDIM;
#pragma unroll
    for (int ni = 0; ni < 16; ni++) {
        *(float2*)&dst0[ni * 8] = make_float2(oacc[ni][0] * inv0, oacc[ni][1] * inv0);
        *(float2*)&dst1[ni * 8] = make_float2(oacc[ni][2] * inv1, oacc[ni][3] * inv1);
    }
}

// ---------------------------------------------------------------------------
extern "C" void kernel_launch(void* const* d_in, const int* in_sizes, int n_in,
                              void* d_out, int out_size)
{
    const float* hs = (const float*)d_in[0];
    const float* Wq = (const float*)d_in[1];
    const float* Wk = (const float*)d_in[2];
    const float* Wv = (const float*)d_in[3];
    const float* Wo = (const float*)d_in[4];
    float* out = (float*)d_out;

    float* aop;
    cudaGetSymbolAddress((void**)&aop, g_ao);
    __half *hsh, *hsl, *fwq, *fwk, *fwv, *fwo, *aoh, *aol;
    cudaGetSymbolAddress((void**)&hsh, g_fhsh); cudaGetSymbolAddress((void**)&hsl, g_fhsl);
    cudaGetSymbolAddress((void**)&fwq, g_fwq);  cudaGetSymbolAddress((void**)&fwk, g_fwk);
    cudaGetSymbolAddress((void**)&fwv, g_fwv);  cudaGetSymbolAddress((void**)&fwo, g_fwo);
    cudaGetSymbolAddress((void**)&aoh, g_faoh); cudaGetSymbolAddress((void**)&aol, g_faol);

    cudaFuncSetAttribute(flash_f16_kernel, cudaFuncAttributeMaxDynamicSharedMemorySize, SMEM_FLASH3);
    cudaFuncSetAttribute(gemm_qkv_kernel, cudaFuncAttributeMaxDynamicSharedMemorySize, SMEM_GEMM);
    cudaFuncSetAttribute(gemm_o_kernel, cudaFuncAttributeMaxDynamicSharedMemorySize, SMEM_GEMM);

    // fp32 -> fp16 conversions
    int n4_hs = NB * S_LEN * HDIM / 4;
    int n4_wq = NH * HD * HDIM / 4;
    int n4_wk = NKV * HD * HDIM / 4;
    cvt_f16s<<<(n4_hs + 255) / 256, 256>>>(hs, hsh, hsl, n4_hs);
    cvt_f16<<<(n4_wq + 255) / 256, 256>>>(Wq, fwq, n4_wq);
    cvt_f16<<<(n4_wk + 255) / 256, 256>>>(Wk, fwk, n4_wk);
    cvt_f16<<<(n4_wk + 255) / 256, 256>>>(Wv, fwv, n4_wk);
    cvt_f16<<<(n4_wq + 255) / 256, 256>>>(Wo, fwo, n4_wq);

    // Fused QKV projections (fp16 2-term, cp.async pipelined)
    gemm_qkv_kernel<<<dim3(24, 32), 256, SMEM_GEMM>>>();

    // RoPE -> fp16; V transpose -> fp16
    const float QSCALE = 1.4426950408889634f / 11.313708498984760f; // log2e/sqrt(128)
    rope_q_f16<<<(NB * NH * S_LEN * 64) / 256, 256>>>(NB * NH * S_LEN * 64, QSCALE);
    rope_k_f16<<<(NB * NKV * S_LEN * 64) / 256, 256>>>(NB * NKV * S_LEN * 64);
    vsplit_f16<<<dim3(S_LEN / 32, HD / 32, NB * NKV), dim3(32, 8)>>>();

    // Attention
    flash_f16_kernel<<<dim3(16, NH, NB), 256, SMEM_FLASH3>>>();

    // Output projection
    int n4_ao = NB * S_LEN * HDIM / 4;
    cvt_f16s<<<(n4_ao + 255) / 256, 256>>>(aop, aoh, aol, n4_ao);
    gemm_o_kernel<<<dim3(16, 32), 256, SMEM_GEMM>>>(out);
}